// round 3
// baseline (speedup 1.0000x reference)
#include <cuda_runtime.h>
#include <cstdint>

// ---------------- problem dims (hardcoded to this problem instance) -------
#define Bd 2
#define Td 2048
#define Cd 512
#define Hd 8
#define HSd 64
#define Ld 4
#define Vd 32000
#define NT (Bd*Td)        // 4096 rows
#define QKVW (3*Cd)       // 1536
#define FFW (4*Cd)        // 2048
#define TTd (Td*Td)       // 4194304

// ---------------- scratch (static device allocations: allowed) -----------
__device__ float g_x   [NT*Cd];
__device__ float g_h   [NT*Cd];
__device__ float g_qkv [NT*QKVW + 512];            // +pad: PV tile reads 128-wide on a 64-wide strip
__device__ float g_wei [Bd*Hd*Td*Td];              // 268 MB attention scores
__device__ float g_att [NT*Cd];
__device__ float g_ff1 [NT*FFW];
__device__ float g_ff2 [NT*Cd];
__device__ float g_wqkv[Ld*Cd*QKVW];               // packed [L][C][3C] qkv weights

// ---------------- embedding ----------------------------------------------
__global__ void embed_kernel(const int* __restrict__ idx,
                             const float* __restrict__ tok,
                             const float* __restrict__ pos,
                             float* __restrict__ out) {
    int r = blockIdx.x;            // 0..NT-1
    int t = r & (Td - 1);
    int token = idx[r];
    int c = threadIdx.x;           // 256 threads, 2 elems each
    const float* tp = tok + (size_t)token * Cd;
    const float* pp = pos + (size_t)t * Cd;
    float* op = out + (size_t)r * Cd;
    op[c]       = tp[c]       + pp[c];
    op[c + 256] = tp[c + 256] + pp[c + 256];
}

// ---------------- qkv weight pack: [H,C,HS] x3 -> [C, 3C] per layer ------
__global__ void pack_qkv_kernel(const float* __restrict__ wq,
                                const float* __restrict__ wk,
                                const float* __restrict__ wv,
                                float* __restrict__ out) {
    int i = blockIdx.x * 256 + threadIdx.x;
    const int total = Ld * Cd * QKVW;
    if (i >= total) return;
    int j = i % QKVW;
    int c = (i / QKVW) % Cd;
    int l = i / (QKVW * Cd);
    int which = j >> 9;            // 0=q,1=k,2=v
    int hj = j & 511;
    int h = hj >> 6;
    int d = hj & 63;
    const float* src = (which == 0) ? wq : (which == 1) ? wk : wv;
    out[i] = src[(((size_t)l * Hd + h) * Cd + c) * HSd + d];
}

// ---------------- layernorm (optionally out = add + LN(in)) --------------
template<bool ADD>
__global__ void ln_kernel(const float* __restrict__ in, float* __restrict__ out,
                          const float* __restrict__ gw, const float* __restrict__ bw,
                          const float* __restrict__ add) {
    int r = blockIdx.x;
    const float* x = in + (size_t)r * Cd;
    int tid = threadIdx.x;         // 256
    float v0 = x[tid], v1 = x[tid + 256];
    __shared__ float rs[256], rq[256];
    rs[tid] = v0 + v1;
    rq[tid] = v0 * v0 + v1 * v1;
    __syncthreads();
    #pragma unroll
    for (int off = 128; off > 0; off >>= 1) {
        if (tid < off) { rs[tid] += rs[tid + off]; rq[tid] += rq[tid + off]; }
        __syncthreads();
    }
    float mean = rs[0] * (1.0f / Cd);
    float var  = rq[0] * (1.0f / Cd) - mean * mean;
    float inv  = rsqrtf(var + 1e-5f);
    float o0 = (v0 - mean) * inv * gw[tid]       + bw[tid];
    float o1 = (v1 - mean) * inv * gw[tid + 256] + bw[tid + 256];
    if (ADD) {
        o0 += add[(size_t)r * Cd + tid];
        o1 += add[(size_t)r * Cd + tid + 256];
    }
    out[(size_t)r * Cd + tid]       = o0;
    out[(size_t)r * Cd + tid + 256] = o1;
}

// ---------------- causal softmax (in-place on g_wei) ----------------------
// Row (bh, t): softmax over s in [0, t]; zero-fill s in (t, 128-aligned end)
// so the PV GEMM (K limited to the diagonal 128-block) reads exact zeros.
__global__ void softmax_kernel(float* __restrict__ wei) {
    int t  = blockIdx.x;
    int bh = blockIdx.y;
    float* row = wei + (size_t)bh * TTd + (size_t)t * Td;
    int len = t + 1;
    int tid = threadIdx.x;         // 256
    __shared__ float sh[Td];
    __shared__ float red[256];

    float mx = -1e30f;
    for (int i = tid; i < len; i += 256) mx = fmaxf(mx, row[i]);
    red[tid] = mx; __syncthreads();
    #pragma unroll
    for (int off = 128; off > 0; off >>= 1) {
        if (tid < off) red[tid] = fmaxf(red[tid], red[tid + off]);
        __syncthreads();
    }
    mx = red[0]; __syncthreads();

    float sum = 0.f;
    for (int i = tid; i < len; i += 256) {
        float e = __expf(row[i] - mx);
        sh[i] = e;
        sum += e;
    }
    red[tid] = sum; __syncthreads();
    #pragma unroll
    for (int off = 128; off > 0; off >>= 1) {
        if (tid < off) red[tid] += red[tid + off];
        __syncthreads();
    }
    float invs = 1.0f / red[0];

    for (int i = tid; i < len; i += 256) row[i] = sh[i] * invs;
    int zend = ((t >> 7) + 1) << 7;       // next multiple of 128
    for (int i = len + tid; i < zend; i += 256) row[i] = 0.0f;
}

// ---------------- templated SGEMM ----------------------------------------
// C[M,N] = A[M,K] * B(+epilogue).  BT: B is [N,K] row-major (use B^T).
// CAUSAL: skip tiles strictly above the diagonal (M==N square, 128 tiles).
// TRILIM: limit K to row0+128 (A's columns are zero beyond the diagonal blk).
// Requirements (all satisfied by our shapes): M%128==0, K%8==0, strips of 8
// output columns are either fully <N or fully >=N (N%64==0), float4-aligned
// lda/ldb/ldc and base offsets (multiples of 4 floats).
#define BM 128
#define BN 128
#define BKt 8
#define TM 8
#define TN 8

template<bool BT, bool BIAS, bool RELU, bool RESID, bool CAUSAL, bool TRILIM>
__global__ __launch_bounds__(256)
void sgemm_kernel(const float* __restrict__ A, const float* __restrict__ B,
                  float* __restrict__ C,
                  const float* __restrict__ bias, const float* __restrict__ resid,
                  int M, int N, int K, int lda, int ldb, int ldc,
                  long long sAo, long long sAi,
                  long long sBo, long long sBi,
                  long long sCo, long long sCi, int nInner) {
    int row0 = blockIdx.y * BM;
    int col0 = blockIdx.x * BN;
    if (CAUSAL && col0 > row0) return;

    int bo = blockIdx.z / nInner;
    int bi = blockIdx.z % nInner;
    A += bo * sAo + bi * sAi;
    B += bo * sBo + bi * sBi;
    C += bo * sCo + bi * sCi;
    const float* Rp = resid;
    if (RESID) Rp += bo * sCo + bi * sCi;

    __shared__ float As[BKt][BM];
    __shared__ float Bs[BKt][BN];

    int tid = threadIdx.x;
    int tx = tid & 15;             // 0..15  (N strip)
    int ty = tid >> 4;             // 0..15  (M strip)

    // loader indices: 128 rows x 8 cols tiles, one float4 per thread
    int arow = tid >> 1;
    int acol = (tid & 1) << 2;
    // normal-B loader: 8 rows x 128 cols
    int brow = tid >> 5;
    int bcol = (tid & 31) << 2;

    float acc[TM][TN];
    #pragma unroll
    for (int i = 0; i < TM; i++)
        #pragma unroll
        for (int j = 0; j < TN; j++) acc[i][j] = 0.0f;

    int Keff = K;
    if (TRILIM) Keff = min(K, row0 + BM);

    for (int k0 = 0; k0 < Keff; k0 += BKt) {
        float4 av = *(const float4*)&A[(size_t)(row0 + arow) * lda + k0 + acol];
        As[acol + 0][arow] = av.x;
        As[acol + 1][arow] = av.y;
        As[acol + 2][arow] = av.z;
        As[acol + 3][arow] = av.w;
        if (BT) {
            float4 bv = *(const float4*)&B[(size_t)(col0 + arow) * ldb + k0 + acol];
            Bs[acol + 0][arow] = bv.x;
            Bs[acol + 1][arow] = bv.y;
            Bs[acol + 2][arow] = bv.z;
            Bs[acol + 3][arow] = bv.w;
        } else {
            float4 bv = *(const float4*)&B[(size_t)(k0 + brow) * ldb + col0 + bcol];
            *(float4*)&Bs[brow][bcol] = bv;
        }
        __syncthreads();

        #pragma unroll
        for (int kk = 0; kk < BKt; kk++) {
            float a[TM], bb[TN];
            #pragma unroll
            for (int i = 0; i < TM; i++) a[i] = As[kk][ty * TM + i];
            #pragma unroll
            for (int j = 0; j < TN; j++) bb[j] = Bs[kk][tx * TN + j];
            #pragma unroll
            for (int i = 0; i < TM; i++)
                #pragma unroll
                for (int j = 0; j < TN; j++)
                    acc[i][j] += a[i] * bb[j];
        }
        __syncthreads();
    }

    int colbase = col0 + tx * TN;
    if (colbase >= N) return;      // partial-N tiles (PV: N=64)

    float4 bv0 = make_float4(0, 0, 0, 0), bv1 = make_float4(0, 0, 0, 0);
    if (BIAS) {
        bv0 = *(const float4*)&bias[colbase];
        bv1 = *(const float4*)&bias[colbase + 4];
    }
    #pragma unroll
    for (int i = 0; i < TM; i++) {
        int row = row0 + ty * TM + i;
        float* cp = &C[(size_t)row * ldc + colbase];
        float4 r0 = make_float4(acc[i][0], acc[i][1], acc[i][2], acc[i][3]);
        float4 r1 = make_float4(acc[i][4], acc[i][5], acc[i][6], acc[i][7]);
        if (BIAS) {
            r0.x += bv0.x; r0.y += bv0.y; r0.z += bv0.z; r0.w += bv0.w;
            r1.x += bv1.x; r1.y += bv1.y; r1.z += bv1.z; r1.w += bv1.w;
        }
        if (RESID) {
            float4 d0 = *(const float4*)&Rp[(size_t)row * ldc + colbase];
            float4 d1 = *(const float4*)&Rp[(size_t)row * ldc + colbase + 4];
            r0.x += d0.x; r0.y += d0.y; r0.z += d0.z; r0.w += d0.w;
            r1.x += d1.x; r1.y += d1.y; r1.z += d1.z; r1.w += d1.w;
        }
        if (RELU) {
            r0.x = fmaxf(r0.x, 0.f); r0.y = fmaxf(r0.y, 0.f);
            r0.z = fmaxf(r0.z, 0.f); r0.w = fmaxf(r0.w, 0.f);
            r1.x = fmaxf(r1.x, 0.f); r1.y = fmaxf(r1.y, 0.f);
            r1.z = fmaxf(r1.z, 0.f); r1.w = fmaxf(r1.w, 0.f);
        }
        *(float4*)cp = r0;
        *(float4*)(cp + 4) = r1;
    }
}

// ---------------- host orchestration --------------------------------------
extern "C" void kernel_launch(void* const* d_in, const int* in_sizes, int n_in,
                              void* d_out, int out_size) {
    const int*   idx     = (const int*)  d_in[0];
    const float* tok_emb = (const float*)d_in[1];
    const float* pos_emb = (const float*)d_in[2];
    const float* ln1_g   = (const float*)d_in[3];
    const float* ln1_b   = (const float*)d_in[4];
    const float* wq      = (const float*)d_in[5];
    const float* wk      = (const float*)d_in[6];
    const float* wv      = (const float*)d_in[7];
    const float* proj_w  = (const float*)d_in[8];
    const float* proj_b  = (const float*)d_in[9];
    const float* ln2_g   = (const float*)d_in[10];
    const float* ln2_b   = (const float*)d_in[11];
    const float* ff_w1   = (const float*)d_in[12];
    const float* ff_b1   = (const float*)d_in[13];
    const float* ff_w2   = (const float*)d_in[14];
    const float* ff_b2   = (const float*)d_in[15];
    const float* ffln_g  = (const float*)d_in[16];
    const float* ffln_b  = (const float*)d_in[17];
    const float* lm_w    = (const float*)d_in[18];
    const float* lm_b    = (const float*)d_in[19];
    float* out = (float*)d_out;

    float *x, *h, *qkv, *wei, *att, *ff1, *ff2, *wqkv;
    cudaGetSymbolAddress((void**)&x,    g_x);
    cudaGetSymbolAddress((void**)&h,    g_h);
    cudaGetSymbolAddress((void**)&qkv,  g_qkv);
    cudaGetSymbolAddress((void**)&wei,  g_wei);
    cudaGetSymbolAddress((void**)&att,  g_att);
    cudaGetSymbolAddress((void**)&ff1,  g_ff1);
    cudaGetSymbolAddress((void**)&ff2,  g_ff2);
    cudaGetSymbolAddress((void**)&wqkv, g_wqkv);

    // embedding + weight packing
    embed_kernel<<<NT, 256>>>(idx, tok_emb, pos_emb, x);
    {
        const int total = Ld * Cd * QKVW;
        pack_qkv_kernel<<<(total + 255) / 256, 256>>>(wq, wk, wv, wqkv);
    }

    for (int l = 0; l < Ld; l++) {
        // LN1
        ln_kernel<false><<<NT, 256>>>(x, h, ln1_g + l * Cd, ln1_b + l * Cd, nullptr);

        // fused QKV GEMM: [4096,512] x [512,1536] -> qkv [4096,1536] ([b,t][q|k|v])
        sgemm_kernel<false, false, false, false, false, false>
            <<<dim3(QKVW / BN, NT / BM, 1), 256>>>(
            h, wqkv + (size_t)l * Cd * QKVW, qkv, nullptr, nullptr,
            NT, QKVW, Cd, Cd, QKVW, QKVW,
            0, 0, 0, 0, 0, 0, 1);

        // scores: wei[b,h,t,s] = Q . K  (BT, causal tile-skip), batched (b,h)
        sgemm_kernel<true, false, false, false, true, false>
            <<<dim3(Td / BN, Td / BM, Bd * Hd), 256>>>(
            qkv /*Q at col 0*/, qkv + Cd /*K at col 512*/, wei, nullptr, nullptr,
            Td, Td, HSd, QKVW, QKVW, Td,
            (long long)Td * QKVW, HSd,
            (long long)Td * QKVW, HSd,
            (long long)Hd * TTd, (long long)TTd, Hd);

        // causal softmax in-place
        softmax_kernel<<<dim3(Td, Bd * Hd), 256>>>(wei);

        // PV: att[b,t,h,d] = wei . V   (K limited to diagonal block)
        sgemm_kernel<false, false, false, false, false, true>
            <<<dim3(1, Td / BM, Bd * Hd), 256>>>(
            wei, qkv + 2 * Cd /*V at col 1024*/, att, nullptr, nullptr,
            Td, HSd, Td, Td, QKVW, Cd,
            (long long)Hd * TTd, (long long)TTd,
            (long long)Td * QKVW, HSd,
            (long long)Td * Cd, HSd, Hd);

        // proj: x = x + att @ proj_w^T + proj_b   (BT + bias + residual)
        sgemm_kernel<true, true, false, true, false, false>
            <<<dim3(Cd / BN, NT / BM, 1), 256>>>(
            att, proj_w + (size_t)l * Cd * Cd, x,
            proj_b + l * Cd, x,
            NT, Cd, Cd, Cd, Cd, Cd,
            0, 0, 0, 0, 0, 0, 1);

        // LN2
        ln_kernel<false><<<NT, 256>>>(x, h, ln2_g + l * Cd, ln2_b + l * Cd, nullptr);

        // FF1: relu(h @ ff_w1 + b1) -> ff1 [4096,2048]
        sgemm_kernel<false, true, true, false, false, false>
            <<<dim3(FFW / BN, NT / BM, 1), 256>>>(
            h, ff_w1 + (size_t)l * Cd * FFW, ff1,
            ff_b1 + l * FFW, nullptr,
            NT, FFW, Cd, Cd, FFW, FFW,
            0, 0, 0, 0, 0, 0, 1);

        // FF2: ff1 @ ff_w2 + b2 -> ff2 [4096,512]
        sgemm_kernel<false, true, false, false, false, false>
            <<<dim3(Cd / BN, NT / BM, 1), 256>>>(
            ff1, ff_w2 + (size_t)l * FFW * Cd, ff2,
            ff_b2 + l * Cd, nullptr,
            NT, Cd, FFW, FFW, Cd, Cd,
            0, 0, 0, 0, 0, 0, 1);

        // x = x + LN(ff2)
        ln_kernel<true><<<NT, 256>>>(ff2, x, ffln_g + l * Cd, ffln_b + l * Cd, x);
    }

    // LM head: logits = x @ lm_w + lm_b -> d_out [4096, 32000]
    sgemm_kernel<false, true, false, false, false, false>
        <<<dim3(Vd / BN, NT / BM, 1), 256>>>(
        x, lm_w, out, lm_b, nullptr,
        NT, Vd, Cd, Cd, Vd, Vd,
        0, 0, 0, 0, 0, 0, 1);
}

// round 7
// speedup vs baseline: 1.5596x; 1.5596x over previous
#include <cuda_runtime.h>
#include <cuda_bf16.h>
#include <cstdint>

#define Bd 2
#define Td 2048
#define Cd 512
#define Hd 8
#define HSd 64
#define Ld 4
#define Vd 32000
#define NT (Bd*Td)
#define QKVW (3*Cd)
#define FFW (4*Cd)
#define TTd (Td*Td)

typedef __nv_bfloat16 bf16;

// ---------------- scratch --------------------------------------------------
__device__ float g_x   [NT*Cd];
__device__ float g_qkv [NT*QKVW + 512];
__device__ float g_wei [Bd*Hd*Td*Td];
__device__ float g_att [NT*Cd];
__device__ float g_ff2 [NT*Cd];
// A3 activations: [rows][3*K] = [Ah | Al | Ah]
__device__ bf16 g_hs3 [NT*3*Cd];
__device__ bf16 g_as3 [NT*3*Cd];
__device__ bf16 g_xs3 [NT*3*Cd];
__device__ bf16 g_f13 [NT*3*FFW];
// B3 weights: [N][3*K] = [Bh | Bh | Bl]
__device__ bf16 g_wqkv3 [Ld*QKVW*3*Cd];
__device__ bf16 g_wproj3[Ld*Cd*3*Cd];
__device__ bf16 g_wff13 [Ld*FFW*3*Cd];
__device__ bf16 g_wff23 [Ld*Cd*3*FFW];
__device__ bf16 g_wlm3  [(size_t)Vd*3*Cd];

// ---------------- helpers --------------------------------------------------
__device__ __forceinline__ uint32_t smem_u32(const void* p) {
    uint32_t a;
    asm("{ .reg .u64 t; cvta.to.shared.u64 t, %1; cvt.u32.u64 %0, t; }" : "=r"(a) : "l"(p));
    return a;
}
__device__ __forceinline__ void cp16(uint32_t d, const void* s) {
    asm volatile("cp.async.cg.shared.global [%0], [%1], 16;" :: "r"(d), "l"(s));
}
#define CP_COMMIT() asm volatile("cp.async.commit_group;" ::: "memory")
template<int N> __device__ __forceinline__ void cp_wait() {
    asm volatile("cp.async.wait_group %0;" :: "n"(N) : "memory");
}
__device__ __forceinline__ void ldsm4(uint32_t& r0, uint32_t& r1, uint32_t& r2,
                                      uint32_t& r3, uint32_t addr) {
    asm volatile("ldmatrix.sync.aligned.m8n8.x4.shared.b16 {%0,%1,%2,%3}, [%4];"
                 : "=r"(r0), "=r"(r1), "=r"(r2), "=r"(r3) : "r"(addr));
}
__device__ __forceinline__ void mma16816(float* c, uint32_t a0, uint32_t a1,
                                         uint32_t a2, uint32_t a3,
                                         uint32_t b0, uint32_t b1) {
    asm volatile(
        "mma.sync.aligned.m16n8k16.row.col.f32.bf16.bf16.f32 "
        "{%0,%1,%2,%3}, {%4,%5,%6,%7}, {%8,%9}, {%0,%1,%2,%3};"
        : "+f"(c[0]), "+f"(c[1]), "+f"(c[2]), "+f"(c[3])
        : "r"(a0), "r"(a1), "r"(a2), "r"(a3), "r"(b0), "r"(b1));
}
__device__ __forceinline__ void split2(float v, bf16& h, bf16& l) {
    h = __float2bfloat16_rn(v);
    l = __float2bfloat16_rn(v - __bfloat162float(h));
}

// ---------------- HMMA GEMM: C[M,N] = A3[M,K3] . B3[N,K3]^T ---------------
// 128x128 tile, BK=32, 256 threads = 8 warps (2 M x 4 N), warp = 64x32.
// smem: padded stride 40 halves (80B, 16B-aligned rows) for ldmatrix.
#define SSTRIDE 40
#define STAGE_H (128*SSTRIDE)          // halves per stage per operand

template<bool BIAS, bool RELU, bool RESID, bool COUT, bool SPLITOUT>
__global__ void __launch_bounds__(256, 1)
hgemm(const bf16* __restrict__ A3, const bf16* __restrict__ B3,
      float* __restrict__ C, const float* __restrict__ bias,
      const float* __restrict__ resid, bf16* __restrict__ S3,
      int M, int N, int K3) {
    __shared__ bf16 As[2][STAGE_H];
    __shared__ bf16 Bs[2][STAGE_H];
    int tid = threadIdx.x;
    int row0 = blockIdx.x * 128;          // x = M (fastest) -> B panel L2-resident
    int col0 = blockIdx.y * 128;
    int lane = tid & 31, wid = tid >> 5;
    int m0 = (wid & 1) * 64, n0 = (wid >> 1) * 32;

    // global->smem loaders: each thread 2 rows x 16B per operand
    int lrow = tid >> 2;                  // 0..63
    int lcol = (tid & 3) * 8;             // 0,8,16,24
    const bf16* pA0 = A3 + (size_t)(row0 + lrow) * K3 + lcol;
    const bf16* pA1 = A3 + (size_t)(row0 + lrow + 64) * K3 + lcol;
    const bf16* pB0 = B3 + (size_t)(col0 + lrow) * K3 + lcol;
    const bf16* pB1 = B3 + (size_t)(col0 + lrow + 64) * K3 + lcol;
    uint32_t sA = smem_u32(As), sB = smem_u32(Bs);
    uint32_t stA0 = sA + (uint32_t)(lrow*SSTRIDE + lcol)*2;
    uint32_t stA1 = sA + (uint32_t)((lrow+64)*SSTRIDE + lcol)*2;
    uint32_t stB0 = sB + (uint32_t)(lrow*SSTRIDE + lcol)*2;
    uint32_t stB1 = sB + (uint32_t)((lrow+64)*SSTRIDE + lcol)*2;
    const uint32_t stageB = STAGE_H * 2;  // bytes

    float acc[4][4][4];
    #pragma unroll
    for (int i = 0; i < 4; i++)
        #pragma unroll
        for (int j = 0; j < 4; j++)
            #pragma unroll
            for (int q = 0; q < 4; q++) acc[i][j][q] = 0.0f;

    int NIT = K3 >> 5;
    cp16(stA0, pA0); cp16(stA1, pA1);
    cp16(stB0, pB0); cp16(stB1, pB1);
    CP_COMMIT();

    // ldmatrix x4 lane->address: lanes 0-15 rows (mats 0,1), 16-31 rows +8 cols (mats 2,3)
    uint32_t aoff = (uint32_t)((m0 + (lane & 15)) * SSTRIDE + (lane >> 4) * 8) * 2;
    uint32_t boff = (uint32_t)((n0 + (lane & 15)) * SSTRIDE + (lane >> 4) * 8) * 2;

    for (int it = 0; it < NIT; it++) {
        int sc = it & 1;
        if (it + 1 < NIT) {
            uint32_t so = (uint32_t)((it + 1) & 1) * stageB;
            int ko = (it + 1) << 5;
            cp16(stA0 + so, pA0 + ko); cp16(stA1 + so, pA1 + ko);
            cp16(stB0 + so, pB0 + ko); cp16(stB1 + so, pB1 + ko);
            CP_COMMIT();
            cp_wait<1>();
        } else {
            cp_wait<0>();
        }
        __syncthreads();
        uint32_t sa = sA + (uint32_t)sc * stageB + aoff;
        uint32_t sb = sB + (uint32_t)sc * stageB + boff;
        #pragma unroll
        for (int kk = 0; kk < 2; kk++) {
            uint32_t a[4][4], b[2][4];
            #pragma unroll
            for (int mi = 0; mi < 4; mi++)
                ldsm4(a[mi][0], a[mi][1], a[mi][2], a[mi][3],
                      sa + (uint32_t)(mi*16*SSTRIDE + kk*16)*2);
            #pragma unroll
            for (int nj = 0; nj < 2; nj++)
                ldsm4(b[nj][0], b[nj][1], b[nj][2], b[nj][3],
                      sb + (uint32_t)(nj*16*SSTRIDE + kk*16)*2);
            #pragma unroll
            for (int mi = 0; mi < 4; mi++) {
                #pragma unroll
                for (int ni = 0; ni < 4; ni++) {
                    int nj = ni >> 1, sub = ni & 1;
                    mma16816(acc[mi][ni], a[mi][0], a[mi][1], a[mi][2], a[mi][3],
                             sub ? b[nj][1] : b[nj][0],
                             sub ? b[nj][3] : b[nj][2]);
                }
            }
        }
        __syncthreads();
    }

    // epilogue: frag (mi,ni): rows r4/r4+8, cols c2,c2+1
    int r4 = lane >> 2, c2 = (lane & 3) * 2;
    #pragma unroll
    for (int mi = 0; mi < 4; mi++) {
        #pragma unroll
        for (int half = 0; half < 2; half++) {
            int row = row0 + m0 + mi*16 + r4 + half*8;
            size_t rowN = (size_t)row * N;
            size_t rowS = (size_t)row * 3 * N;
            #pragma unroll
            for (int ni = 0; ni < 4; ni++) {
                int col = col0 + n0 + ni*8 + c2;
                float v0 = acc[mi][ni][half*2 + 0];
                float v1 = acc[mi][ni][half*2 + 1];
                if (BIAS) { v0 += bias[col]; v1 += bias[col + 1]; }
                if (RESID) {
                    float2 rv = *(const float2*)&resid[rowN + col];
                    v0 += rv.x; v1 += rv.y;
                }
                if (RELU) { v0 = fmaxf(v0, 0.f); v1 = fmaxf(v1, 0.f); }
                if (COUT) *(float2*)&C[rowN + col] = make_float2(v0, v1);
                if (SPLITOUT) {
                    bf16 h0, l0, h1, l1;
                    split2(v0, h0, l0); split2(v1, h1, l1);
                    __nv_bfloat162 ph; ph.x = h0; ph.y = h1;
                    __nv_bfloat162 pl; pl.x = l0; pl.y = l1;
                    *(__nv_bfloat162*)&S3[rowS + col]         = ph;
                    *(__nv_bfloat162*)&S3[rowS + N + col]     = pl;
                    *(__nv_bfloat162*)&S3[rowS + 2*N + col]   = ph;
                }
            }
        }
    }
}

// ---------------- small kernels --------------------------------------------
__global__ void embed_kernel(const int* __restrict__ idx, const float* __restrict__ tok,
                             const float* __restrict__ pos, float* __restrict__ out) {
    int r = blockIdx.x;
    int t = r & (Td - 1);
    int token = idx[r];
    int c = threadIdx.x;
    const float* tp = tok + (size_t)token * Cd;
    const float* pp = pos + (size_t)t * Cd;
    float* op = out + (size_t)r * Cd;
    op[c] = tp[c] + pp[c];
    op[c + 256] = tp[c + 256] + pp[c + 256];
}

// LN -> fp32 out (optional) + A3 split out
template<bool ADD, bool FOUT>
__global__ void ln_kernel(const float* __restrict__ in, float* __restrict__ out,
                          const float* __restrict__ gw, const float* __restrict__ bw,
                          const float* __restrict__ add, bf16* __restrict__ s3) {
    int r = blockIdx.x;
    const float* x = in + (size_t)r * Cd;
    int tid = threadIdx.x;
    float v0 = x[tid], v1 = x[tid + 256];
    __shared__ float rs[256], rq[256];
    rs[tid] = v0 + v1;
    rq[tid] = v0 * v0 + v1 * v1;
    __syncthreads();
    #pragma unroll
    for (int off = 128; off > 0; off >>= 1) {
        if (tid < off) { rs[tid] += rs[tid+off]; rq[tid] += rq[tid+off]; }
        __syncthreads();
    }
    float mean = rs[0] * (1.0f / Cd);
    float var = rq[0] * (1.0f / Cd) - mean * mean;
    float inv = rsqrtf(var + 1e-5f);
    float o0 = (v0 - mean) * inv * gw[tid] + bw[tid];
    float o1 = (v1 - mean) * inv * gw[tid+256] + bw[tid+256];
    if (ADD) {
        o0 += add[(size_t)r * Cd + tid];
        o1 += add[(size_t)r * Cd + tid + 256];
    }
    if (FOUT) {
        out[(size_t)r * Cd + tid] = o0;
        out[(size_t)r * Cd + tid + 256] = o1;
    }
    bf16 h, l;
    size_t base = (size_t)r * 3 * Cd;
    split2(o0, h, l);
    s3[base + tid] = h; s3[base + Cd + tid] = l; s3[base + 2*Cd + tid] = h;
    split2(o1, h, l);
    s3[base + tid + 256] = h; s3[base + Cd + tid + 256] = l; s3[base + 2*Cd + tid + 256] = h;
}

__global__ void softmax_kernel(float* __restrict__ wei) {
    int t = blockIdx.x, bh = blockIdx.y;
    float* row = wei + (size_t)bh * TTd + (size_t)t * Td;
    int len = t + 1, tid = threadIdx.x;
    __shared__ float sh[Td];
    __shared__ float red[256];
    float mx = -1e30f;
    for (int i = tid; i < len; i += 256) mx = fmaxf(mx, row[i]);
    red[tid] = mx; __syncthreads();
    #pragma unroll
    for (int off = 128; off > 0; off >>= 1) {
        if (tid < off) red[tid] = fmaxf(red[tid], red[tid+off]);
        __syncthreads();
    }
    mx = red[0]; __syncthreads();
    float sum = 0.f;
    for (int i = tid; i < len; i += 256) {
        float e = __expf(row[i] - mx);
        sh[i] = e; sum += e;
    }
    red[tid] = sum; __syncthreads();
    #pragma unroll
    for (int off = 128; off > 0; off >>= 1) {
        if (tid < off) red[tid] += red[tid+off];
        __syncthreads();
    }
    float invs = 1.0f / red[0];
    for (int i = tid; i < len; i += 256) row[i] = sh[i] * invs;
    int zend = ((t >> 7) + 1) << 7;
    for (int i = len + tid; i < zend; i += 256) row[i] = 0.0f;
}

// fp32 [rows][W] -> A3 [rows][3W] = [h | l | h]
__global__ void split_a3(const float* __restrict__ in, bf16* __restrict__ o3,
                         int n, int W) {
    int i = blockIdx.x * 256 + threadIdx.x;
    if (i >= n) return;
    int r = i / W, k = i - r * W;
    bf16 h, l; split2(in[i], h, l);
    size_t base = (size_t)r * 3 * W;
    o3[base + k] = h; o3[base + W + k] = l; o3[base + 2*W + k] = h;
}
// qkv weights [L,H,C,HS]x3 -> B3 [L][N=1536][3*Cd] = [h | h | l]
__global__ void prep_qkv_w(const float* __restrict__ wq, const float* __restrict__ wk,
                           const float* __restrict__ wv, bf16* __restrict__ o3) {
    int i = blockIdx.x * 256 + threadIdx.x;
    if (i >= Ld * QKVW * Cd) return;
    int k = i % Cd;
    int n = (i / Cd) % QKVW;
    int l = i / (Cd * QKVW);
    int which = n >> 9, h = (n >> 6) & 7, d = n & 63;
    const float* src = (which == 0) ? wq : (which == 1) ? wk : wv;
    float v = src[(((size_t)l * Hd + h) * Cd + k) * HSd + d];
    bf16 hh, ll; split2(v, hh, ll);
    size_t base = ((size_t)l * QKVW + n) * 3 * Cd;
    o3[base + k] = hh; o3[base + Cd + k] = hh; o3[base + 2*Cd + k] = ll;
}
// row-major [N][K] -> B3 [N][3K] = [h | h | l]
__global__ void split_b3(const float* __restrict__ in, bf16* __restrict__ o3,
                         int n, int W) {
    int i = blockIdx.x * 256 + threadIdx.x;
    if (i >= n) return;
    int r = i / W, k = i - r * W;
    bf16 h, l; split2(in[i], h, l);
    size_t base = (size_t)r * 3 * W;
    o3[base + k] = h; o3[base + W + k] = h; o3[base + 2*W + k] = l;
}
// [K,N] slab per z -> B3 [N][3K] = [h | h | l]
__global__ void transpose_b3(const float* __restrict__ in, bf16* __restrict__ o3,
                             int K, int N) {
    __shared__ float tsm[32][33];
    in += (size_t)blockIdx.z * K * N;
    o3 += (size_t)blockIdx.z * N * 3 * K;
    int n0 = blockIdx.x * 32, k0 = blockIdx.y * 32;
    for (int j = threadIdx.y; j < 32; j += 8)
        tsm[j][threadIdx.x] = in[(size_t)(k0 + j) * N + n0 + threadIdx.x];
    __syncthreads();
    for (int i = threadIdx.y; i < 32; i += 8) {
        float v = tsm[threadIdx.x][i];
        bf16 h, l; split2(v, h, l);
        size_t base = (size_t)(n0 + i) * 3 * K;
        int k = k0 + threadIdx.x;
        o3[base + k] = h; o3[base + K + k] = h; o3[base + 2*K + k] = l;
    }
}

// ---------------- fp32 SGEMM (attention), batched over z=(b*Hd+h) ---------
#define BM 128
#define BN 128
#define BKt 8
template<bool BT, bool CAUSAL, bool TRILIM>
__global__ __launch_bounds__(256)
void sgemm_kernel(const float* __restrict__ A, const float* __restrict__ B,
                  float* __restrict__ C,
                  int M, int N, int K, int lda, int ldb, int ldc,
                  long long sAb, long long sAh,
                  long long sBb, long long sBh,
                  long long sCb, long long sCh) {
    int row0 = blockIdx.y * BM;
    int col0 = blockIdx.x * BN;
    if (CAUSAL && col0 > row0) return;
    int z = blockIdx.z, bb = z >> 3, hh = z & 7;
    A += (size_t)bb * sAb + (size_t)hh * sAh;
    B += (size_t)bb * sBb + (size_t)hh * sBh;
    C += (size_t)bb * sCb + (size_t)hh * sCh;
    __shared__ float As[BKt][BM];
    __shared__ float Bs[BKt][BN];
    int tid = threadIdx.x;
    int tx = tid & 15, ty = tid >> 4;
    int arow = tid >> 1, acol = (tid & 1) << 2;
    int brow = tid >> 5, bcol = (tid & 31) << 2;
    float acc[8][8];
    #pragma unroll
    for (int i = 0; i < 8; i++)
        #pragma unroll
        for (int j = 0; j < 8; j++) acc[i][j] = 0.0f;
    int Keff = TRILIM ? min(K, row0 + BM) : K;
    for (int k0 = 0; k0 < Keff; k0 += BKt) {
        float4 av = *(const float4*)&A[(size_t)(row0 + arow) * lda + k0 + acol];
        As[acol+0][arow] = av.x; As[acol+1][arow] = av.y;
        As[acol+2][arow] = av.z; As[acol+3][arow] = av.w;
        if (BT) {
            float4 bv = *(const float4*)&B[(size_t)(col0 + arow) * ldb + k0 + acol];
            Bs[acol+0][arow] = bv.x; Bs[acol+1][arow] = bv.y;
            Bs[acol+2][arow] = bv.z; Bs[acol+3][arow] = bv.w;
        } else {
            float4 bv = *(const float4*)&B[(size_t)(k0 + brow) * ldb + col0 + bcol];
            *(float4*)&Bs[brow][bcol] = bv;
        }
        __syncthreads();
        #pragma unroll
        for (int kk = 0; kk < BKt; kk++) {
            float a[8], bb2[8];
            #pragma unroll
            for (int i = 0; i < 8; i++) a[i] = As[kk][ty*8 + i];
            #pragma unroll
            for (int j = 0; j < 8; j++) bb2[j] = Bs[kk][tx*8 + j];
            #pragma unroll
            for (int i = 0; i < 8; i++)
                #pragma unroll
                for (int j = 0; j < 8; j++)
                    acc[i][j] += a[i] * bb2[j];
        }
        __syncthreads();
    }
    int colbase = col0 + tx * 8;
    if (colbase >= N) return;
    #pragma unroll
    for (int i = 0; i < 8; i++) {
        int row = row0 + ty * 8 + i;
        float* cp = &C[(size_t)row * ldc + colbase];
        *(float4*)cp     = make_float4(acc[i][0], acc[i][1], acc[i][2], acc[i][3]);
        *(float4*)(cp+4) = make_float4(acc[i][4], acc[i][5], acc[i][6], acc[i][7]);
    }
}

// ---------------- host -----------------------------------------------------
extern "C" void kernel_launch(void* const* d_in, const int* in_sizes, int n_in,
                              void* d_out, int out_size) {
    const int*   idx     = (const int*)  d_in[0];
    const float* tok_emb = (const float*)d_in[1];
    const float* pos_emb = (const float*)d_in[2];
    const float* ln1_g   = (const float*)d_in[3];
    const float* ln1_b   = (const float*)d_in[4];
    const float* wq      = (const float*)d_in[5];
    const float* wk      = (const float*)d_in[6];
    const float* wv      = (const float*)d_in[7];
    const float* proj_w  = (const float*)d_in[8];
    const float* proj_b  = (const float*)d_in[9];
    const float* ln2_g   = (const float*)d_in[10];
    const float* ln2_b   = (const float*)d_in[11];
    const float* ff_w1   = (const float*)d_in[12];
    const float* ff_b1   = (const float*)d_in[13];
    const float* ff_w2   = (const float*)d_in[14];
    const float* ff_b2   = (const float*)d_in[15];
    const float* ffln_g  = (const float*)d_in[16];
    const float* ffln_b  = (const float*)d_in[17];
    const float* lm_w    = (const float*)d_in[18];
    const float* lm_b    = (const float*)d_in[19];
    float* out = (float*)d_out;

    float *x, *qkv, *wei, *att, *ff2;
    cudaGetSymbolAddress((void**)&x,   g_x);
    cudaGetSymbolAddress((void**)&qkv, g_qkv);
    cudaGetSymbolAddress((void**)&wei, g_wei);
    cudaGetSymbolAddress((void**)&att, g_att);
    cudaGetSymbolAddress((void**)&ff2, g_ff2);
    bf16 *hs3, *as3, *xs3, *f13, *wqkv3, *wproj3, *wff13, *wff23, *wlm3;
    cudaGetSymbolAddress((void**)&hs3,   g_hs3);
    cudaGetSymbolAddress((void**)&as3,   g_as3);
    cudaGetSymbolAddress((void**)&xs3,   g_xs3);
    cudaGetSymbolAddress((void**)&f13,   g_f13);
    cudaGetSymbolAddress((void**)&wqkv3, g_wqkv3);
    cudaGetSymbolAddress((void**)&wproj3,g_wproj3);
    cudaGetSymbolAddress((void**)&wff13, g_wff13);
    cudaGetSymbolAddress((void**)&wff23, g_wff23);
    cudaGetSymbolAddress((void**)&wlm3,  g_wlm3);

    embed_kernel<<<NT, 256>>>(idx, tok_emb, pos_emb, x);
    prep_qkv_w<<<(Ld*QKVW*Cd + 255)/256, 256>>>(wq, wk, wv, wqkv3);
    split_b3<<<(Ld*Cd*Cd + 255)/256, 256>>>(proj_w, wproj3, Ld*Cd*Cd, Cd);
    transpose_b3<<<dim3(FFW/32, Cd/32, Ld), dim3(32,8)>>>(ff_w1, wff13, Cd, FFW);
    transpose_b3<<<dim3(Cd/32, FFW/32, Ld), dim3(32,8)>>>(ff_w2, wff23, FFW, Cd);
    transpose_b3<<<dim3(Vd/32, Cd/32, 1),  dim3(32,8)>>>(lm_w, wlm3, Cd, Vd);

    for (int l = 0; l < Ld; l++) {
        ln_kernel<false,false><<<NT, 256>>>(x, nullptr, ln1_g + l*Cd, ln1_b + l*Cd,
                                            nullptr, hs3);
        // QKV: [4096,1536] (no bias)
        hgemm<false,false,false,true,false><<<dim3(NT/128, QKVW/128), 256>>>(
            hs3, wqkv3 + (size_t)l*QKVW*3*Cd, qkv, nullptr, nullptr, nullptr,
            NT, QKVW, 3*Cd);
        // scores: Q.K^T (causal tile skip)
        sgemm_kernel<true, true, false><<<dim3(Td/BN, Td/BM, Bd*Hd), 256>>>(
            qkv, qkv + Cd, wei, Td, Td, HSd, QKVW, QKVW, Td,
            (long long)Td*QKVW, (long long)HSd,
            (long long)Td*QKVW, (long long)HSd,
            (long long)Hd*TTd,  (long long)TTd);
        softmax_kernel<<<dim3(Td, Bd*Hd), 256>>>(wei);
        // PV (K limited to diagonal block)
        sgemm_kernel<false, false, true><<<dim3(1, Td/BM, Bd*Hd), 256>>>(
            wei, qkv + 2*Cd, att, Td, HSd, Td, Td, QKVW, Cd,
            (long long)Hd*TTd,  (long long)TTd,
            (long long)Td*QKVW, (long long)HSd,
            (long long)Td*Cd,   (long long)HSd);
        split_a3<<<(NT*Cd + 255)/256, 256>>>(att, as3, NT*Cd, Cd);
        // proj + bias + residual -> x
        hgemm<true,false,true,true,false><<<dim3(NT/128, Cd/128), 256>>>(
            as3, wproj3 + (size_t)l*Cd*3*Cd, x, proj_b + l*Cd, x, nullptr,
            NT, Cd, 3*Cd);
        ln_kernel<false,false><<<NT, 256>>>(x, nullptr, ln2_g + l*Cd, ln2_b + l*Cd,
                                            nullptr, hs3);
        // FF1 (+bias, relu) -> A3 split direct
        hgemm<true,true,false,false,true><<<dim3(NT/128, FFW/128), 256>>>(
            hs3, wff13 + (size_t)l*FFW*3*Cd, nullptr, ff_b1 + l*FFW, nullptr, f13,
            NT, FFW, 3*Cd);
        // FF2 (+bias) -> ff2
        hgemm<true,false,false,true,false><<<dim3(NT/128, Cd/128), 256>>>(
            f13, wff23 + (size_t)l*Cd*3*FFW, ff2, ff_b2 + l*Cd, nullptr, nullptr,
            NT, Cd, 3*FFW);
        // x = x + LN(ff2); split x for LM head
        ln_kernel<true,true><<<NT, 256>>>(ff2, x, ffln_g + l*Cd, ffln_b + l*Cd,
                                          x, xs3);
    }
    // LM head
    hgemm<true,false,false,true,false><<<dim3(NT/128, Vd/128), 256>>>(
        xs3, wlm3, out, lm_b, nullptr, nullptr, NT, Vd, 3*Cd);
}

// round 8
// speedup vs baseline: 2.4123x; 1.5467x over previous
#include <cuda_runtime.h>
#include <cuda_bf16.h>
#include <cstdint>

#define Bd 2
#define Td 2048
#define Cd 512
#define Hd 8
#define HSd 64
#define Ld 4
#define Vd 32000
#define NT (Bd*Td)
#define QKVW (3*Cd)
#define FFW (4*Cd)
#define QKV3W (3*QKVW)       // 4608

typedef __nv_bfloat16 bf16;

// ---------------- scratch --------------------------------------------------
__device__ float g_x   [NT*Cd];
__device__ float g_ff2 [NT*Cd];
__device__ bf16 g_qkv3[(size_t)NT*QKV3W];      // [Qh Kh Vh | Ql Kl Vl | Qh Kh Vh]
__device__ bf16 g_hs3 [NT*3*Cd];
__device__ bf16 g_as3 [NT*3*Cd];
__device__ bf16 g_xs3 [NT*3*Cd];
__device__ bf16 g_f13 [NT*3*FFW];
__device__ bf16 g_wqkv3 [Ld*QKVW*3*Cd];
__device__ bf16 g_wproj3[Ld*Cd*3*Cd];
__device__ bf16 g_wff13 [Ld*FFW*3*Cd];
__device__ bf16 g_wff23 [Ld*Cd*3*FFW];
__device__ bf16 g_wlm3  [(size_t)Vd*3*Cd];

// ---------------- helpers --------------------------------------------------
__device__ __forceinline__ uint32_t smem_u32(const void* p) {
    uint32_t a;
    asm("{ .reg .u64 t; cvta.to.shared.u64 t, %1; cvt.u32.u64 %0, t; }" : "=r"(a) : "l"(p));
    return a;
}
__device__ __forceinline__ void cp16(uint32_t d, const void* s) {
    asm volatile("cp.async.cg.shared.global [%0], [%1], 16;" :: "r"(d), "l"(s));
}
#define CP_COMMIT() asm volatile("cp.async.commit_group;" ::: "memory")
template<int N> __device__ __forceinline__ void cp_wait() {
    asm volatile("cp.async.wait_group %0;" :: "n"(N) : "memory");
}
__device__ __forceinline__ void ldsm4(uint32_t& r0, uint32_t& r1, uint32_t& r2,
                                      uint32_t& r3, uint32_t addr) {
    asm volatile("ldmatrix.sync.aligned.m8n8.x4.shared.b16 {%0,%1,%2,%3}, [%4];"
                 : "=r"(r0), "=r"(r1), "=r"(r2), "=r"(r3) : "r"(addr));
}
__device__ __forceinline__ void ldsm4t(uint32_t& r0, uint32_t& r1, uint32_t& r2,
                                       uint32_t& r3, uint32_t addr) {
    asm volatile("ldmatrix.sync.aligned.m8n8.x4.trans.shared.b16 {%0,%1,%2,%3}, [%4];"
                 : "=r"(r0), "=r"(r1), "=r"(r2), "=r"(r3) : "r"(addr));
}
__device__ __forceinline__ void mma16816(float* c, uint32_t a0, uint32_t a1,
                                         uint32_t a2, uint32_t a3,
                                         uint32_t b0, uint32_t b1) {
    asm volatile(
        "mma.sync.aligned.m16n8k16.row.col.f32.bf16.bf16.f32 "
        "{%0,%1,%2,%3}, {%4,%5,%6,%7}, {%8,%9}, {%0,%1,%2,%3};"
        : "+f"(c[0]), "+f"(c[1]), "+f"(c[2]), "+f"(c[3])
        : "r"(a0), "r"(a1), "r"(a2), "r"(a3), "r"(b0), "r"(b1));
}
__device__ __forceinline__ void split2(float v, bf16& h, bf16& l) {
    h = __float2bfloat16_rn(v);
    l = __float2bfloat16_rn(v - __bfloat162float(h));
}
__device__ __forceinline__ uint32_t packbf(float x, float y) {
    __nv_bfloat162 t = __floats2bfloat162_rn(x, y);
    return *(uint32_t*)&t;
}

// ---------------- HMMA GEMM: C[M,N] = A3[M,K3] . B3[N,K3]^T ---------------
#define SSTRIDE 40
#define STAGE_H (128*SSTRIDE)

template<bool BIAS, bool RELU, bool RESID, bool COUT, bool SPLITOUT>
__global__ void __launch_bounds__(256, 1)
hgemm(const bf16* __restrict__ A3, const bf16* __restrict__ B3,
      float* __restrict__ C, const float* __restrict__ bias,
      const float* __restrict__ resid, bf16* __restrict__ S3,
      int M, int N, int K3) {
    __shared__ bf16 As[2][STAGE_H];
    __shared__ bf16 Bs[2][STAGE_H];
    int tid = threadIdx.x;
    int row0 = blockIdx.x * 128;
    int col0 = blockIdx.y * 128;
    int lane = tid & 31, wid = tid >> 5;
    int m0 = (wid & 1) * 64, n0 = (wid >> 1) * 32;

    int lrow = tid >> 2;
    int lcol = (tid & 3) * 8;
    const bf16* pA0 = A3 + (size_t)(row0 + lrow) * K3 + lcol;
    const bf16* pA1 = A3 + (size_t)(row0 + lrow + 64) * K3 + lcol;
    const bf16* pB0 = B3 + (size_t)(col0 + lrow) * K3 + lcol;
    const bf16* pB1 = B3 + (size_t)(col0 + lrow + 64) * K3 + lcol;
    uint32_t sA = smem_u32(As), sB = smem_u32(Bs);
    uint32_t stA0 = sA + (uint32_t)(lrow*SSTRIDE + lcol)*2;
    uint32_t stA1 = sA + (uint32_t)((lrow+64)*SSTRIDE + lcol)*2;
    uint32_t stB0 = sB + (uint32_t)(lrow*SSTRIDE + lcol)*2;
    uint32_t stB1 = sB + (uint32_t)((lrow+64)*SSTRIDE + lcol)*2;
    const uint32_t stageB = STAGE_H * 2;

    float acc[4][4][4];
    #pragma unroll
    for (int i = 0; i < 4; i++)
        #pragma unroll
        for (int j = 0; j < 4; j++)
            #pragma unroll
            for (int q = 0; q < 4; q++) acc[i][j][q] = 0.0f;

    int NIT = K3 >> 5;
    cp16(stA0, pA0); cp16(stA1, pA1);
    cp16(stB0, pB0); cp16(stB1, pB1);
    CP_COMMIT();

    uint32_t aoff = (uint32_t)((m0 + (lane & 15)) * SSTRIDE + (lane >> 4) * 8) * 2;
    uint32_t boff = (uint32_t)((n0 + (lane & 15)) * SSTRIDE + (lane >> 4) * 8) * 2;

    for (int it = 0; it < NIT; it++) {
        int sc = it & 1;
        if (it + 1 < NIT) {
            uint32_t so = (uint32_t)((it + 1) & 1) * stageB;
            int ko = (it + 1) << 5;
            cp16(stA0 + so, pA0 + ko); cp16(stA1 + so, pA1 + ko);
            cp16(stB0 + so, pB0 + ko); cp16(stB1 + so, pB1 + ko);
            CP_COMMIT();
            cp_wait<1>();
        } else {
            cp_wait<0>();
        }
        __syncthreads();
        uint32_t sa = sA + (uint32_t)sc * stageB + aoff;
        uint32_t sb = sB + (uint32_t)sc * stageB + boff;
        #pragma unroll
        for (int kk = 0; kk < 2; kk++) {
            uint32_t a[4][4], b[2][4];
            #pragma unroll
            for (int mi = 0; mi < 4; mi++)
                ldsm4(a[mi][0], a[mi][1], a[mi][2], a[mi][3],
                      sa + (uint32_t)(mi*16*SSTRIDE + kk*16)*2);
            #pragma unroll
            for (int nj = 0; nj < 2; nj++)
                ldsm4(b[nj][0], b[nj][1], b[nj][2], b[nj][3],
                      sb + (uint32_t)(nj*16*SSTRIDE + kk*16)*2);
            #pragma unroll
            for (int mi = 0; mi < 4; mi++) {
                #pragma unroll
                for (int ni = 0; ni < 4; ni++) {
                    int nj = ni >> 1, sub = ni & 1;
                    mma16816(acc[mi][ni], a[mi][0], a[mi][1], a[mi][2], a[mi][3],
                             sub ? b[nj][1] : b[nj][0],
                             sub ? b[nj][3] : b[nj][2]);
                }
            }
        }
        __syncthreads();
    }

    int r4 = lane >> 2, c2 = (lane & 3) * 2;
    #pragma unroll
    for (int mi = 0; mi < 4; mi++) {
        #pragma unroll
        for (int half = 0; half < 2; half++) {
            int row = row0 + m0 + mi*16 + r4 + half*8;
            size_t rowN = (size_t)row * N;
            size_t rowS = (size_t)row * 3 * N;
            #pragma unroll
            for (int ni = 0; ni < 4; ni++) {
                int col = col0 + n0 + ni*8 + c2;
                float v0 = acc[mi][ni][half*2 + 0];
                float v1 = acc[mi][ni][half*2 + 1];
                if (BIAS) { v0 += bias[col]; v1 += bias[col + 1]; }
                if (RESID) {
                    float2 rv = *(const float2*)&resid[rowN + col];
                    v0 += rv.x; v1 += rv.y;
                }
                if (RELU) { v0 = fmaxf(v0, 0.f); v1 = fmaxf(v1, 0.f); }
                if (COUT) *(float2*)&C[rowN + col] = make_float2(v0, v1);
                if (SPLITOUT) {
                    bf16 h0, l0, h1, l1;
                    split2(v0, h0, l0); split2(v1, h1, l1);
                    __nv_bfloat162 ph; ph.x = h0; ph.y = h1;
                    __nv_bfloat162 pl; pl.x = l0; pl.y = l1;
                    *(__nv_bfloat162*)&S3[rowS + col]       = ph;
                    *(__nv_bfloat162*)&S3[rowS + N + col]   = pl;
                    *(__nv_bfloat162*)&S3[rowS + 2*N + col] = ph;
                }
            }
        }
    }
}

// ---------------- flash attention ------------------------------------------
// grid (16 q-tiles, 16 bh). 256 thr / 8 warps, warp = 16 q-rows.
// smem halves layout: Qh@0, Ql@9216, then 2 KV stages of 36864:
//   per stage: Kh@0, Kl@9216, Vh@18432, Vl@27648. PAD=72 halves/row.
#define FPAD 72
#define FQL 9216
#define FKV 18432
#define FSTG 36864
#define FLASH_SMEM ((FKV + 2*FSTG) * 2)

__global__ void __launch_bounds__(256, 1)
flash_kernel(const bf16* __restrict__ qkv3, bf16* __restrict__ as3) {
    extern __shared__ bf16 fsm[];
    uint32_t sbase = smem_u32(fsm);
    int tid = threadIdx.x, lane = tid & 31, wid = tid >> 5;
    int qt = blockIdx.x, bh = blockIdx.y;
    int b = bh >> 3, h = bh & 7;
    int grow0 = b * Td + qt * 128;
    int m0 = wid * 16;

    // loaders: 2 threads/row, 32 halves each
    int r2 = tid >> 1, c32 = (tid & 1) * 32;
    {   // Q (hi at col h*64, lo at 1536+h*64)
        const bf16* src = qkv3 + (size_t)(grow0 + r2) * QKV3W + c32;
        uint32_t d = sbase + (uint32_t)(r2 * FPAD + c32) * 2;
        #pragma unroll
        for (int j = 0; j < 4; j++) {
            cp16(d + j*16,           src + h*64 + j*8);
            cp16(d + FQL*2 + j*16,   src + 1536 + h*64 + j*8);
        }
    }
    // K/V stage loader
    auto load_kv = [&](int stage, int kv) {
        const bf16* src = qkv3 + (size_t)(b * Td + kv * 128 + r2) * QKV3W + c32;
        uint32_t d = sbase + (uint32_t)(FKV + stage*FSTG + r2 * FPAD + c32) * 2;
        #pragma unroll
        for (int j = 0; j < 4; j++) {
            cp16(d + j*16,            src + 512 + h*64 + j*8);         // Kh
            cp16(d + FQL*2 + j*16,    src + 1536 + 512 + h*64 + j*8);  // Kl
            cp16(d + FQL*4 + j*16,    src + 1024 + h*64 + j*8);        // Vh
            cp16(d + FQL*6 + j*16,    src + 1536 + 1024 + h*64 + j*8); // Vl
        }
    };
    load_kv(0, 0);
    CP_COMMIT();

    float m[2] = {-1e30f, -1e30f}, l[2] = {0.f, 0.f};
    float O[8][4];
    #pragma unroll
    for (int f = 0; f < 8; f++)
        #pragma unroll
        for (int e = 0; e < 4; e++) O[f][e] = 0.f;

    int nkv = qt + 1;
    int r4 = lane >> 2, c2 = (lane & 3) * 2;
    int rowg0 = qt*128 + m0 + r4;            // global q position (within seq)

    for (int kv = 0; kv < nkv; kv++) {
        if (kv + 1 < nkv) { load_kv((kv + 1) & 1, kv + 1); CP_COMMIT(); cp_wait<1>(); }
        else cp_wait<0>();
        __syncthreads();
        uint32_t kb = sbase + (uint32_t)(FKV + (kv & 1) * FSTG) * 2;

        // ---- S = Qh.Kh^T + Ql.Kh^T + Qh.Kl^T ----
        float S[16][4];
        #pragma unroll
        for (int f = 0; f < 16; f++)
            #pragma unroll
            for (int e = 0; e < 4; e++) S[f][e] = 0.f;
        #pragma unroll
        for (int kc = 0; kc < 4; kc++) {
            uint32_t qa = sbase + (uint32_t)((m0 + (lane & 15)) * FPAD + kc*16 + (lane >> 4)*8) * 2;
            uint32_t aH[4], aL[4];
            ldsm4(aH[0], aH[1], aH[2], aH[3], qa);
            ldsm4(aL[0], aL[1], aL[2], aL[3], qa + FQL*2);
            #pragma unroll
            for (int ng = 0; ng < 8; ng++) {
                uint32_t ka = kb + (uint32_t)((ng*16 + (lane & 15)) * FPAD + kc*16 + (lane >> 4)*8) * 2;
                uint32_t bH[4], bL[4];
                ldsm4(bH[0], bH[1], bH[2], bH[3], ka);
                ldsm4(bL[0], bL[1], bL[2], bL[3], ka + FQL*2);
                #pragma unroll
                for (int sub = 0; sub < 2; sub++) {
                    float* c = S[ng*2 + sub];
                    uint32_t b0 = sub ? bH[1] : bH[0], b1 = sub ? bH[3] : bH[2];
                    uint32_t l0 = sub ? bL[1] : bL[0], l1 = sub ? bL[3] : bL[2];
                    mma16816(c, aH[0], aH[1], aH[2], aH[3], b0, b1);
                    mma16816(c, aL[0], aL[1], aL[2], aL[3], b0, b1);
                    mma16816(c, aH[0], aH[1], aH[2], aH[3], l0, l1);
                }
            }
        }

        // ---- causal mask (diagonal tile only) ----
        if (kv == qt) {
            #pragma unroll
            for (int f = 0; f < 16; f++) {
                int colb = kv*128 + f*8 + c2;
                #pragma unroll
                for (int e = 0; e < 4; e++) {
                    int col = colb + (e & 1);
                    int row = rowg0 + ((e & 2) ? 8 : 0);
                    if (col > row) S[f][e] = -1e30f;
                }
            }
        }

        // ---- online softmax ----
        float mx0 = -1e30f, mx1 = -1e30f;
        #pragma unroll
        for (int f = 0; f < 16; f++) {
            mx0 = fmaxf(mx0, fmaxf(S[f][0], S[f][1]));
            mx1 = fmaxf(mx1, fmaxf(S[f][2], S[f][3]));
        }
        mx0 = fmaxf(mx0, __shfl_xor_sync(0xffffffff, mx0, 1));
        mx0 = fmaxf(mx0, __shfl_xor_sync(0xffffffff, mx0, 2));
        mx1 = fmaxf(mx1, __shfl_xor_sync(0xffffffff, mx1, 1));
        mx1 = fmaxf(mx1, __shfl_xor_sync(0xffffffff, mx1, 2));
        float mn0 = fmaxf(m[0], mx0), mn1 = fmaxf(m[1], mx1);
        float a0 = __expf(m[0] - mn0), a1 = __expf(m[1] - mn1);
        m[0] = mn0; m[1] = mn1;
        float s0 = 0.f, s1 = 0.f;
        #pragma unroll
        for (int f = 0; f < 16; f++) {
            S[f][0] = __expf(S[f][0] - mn0);
            S[f][1] = __expf(S[f][1] - mn0);
            S[f][2] = __expf(S[f][2] - mn1);
            S[f][3] = __expf(S[f][3] - mn1);
            s0 += S[f][0] + S[f][1];
            s1 += S[f][2] + S[f][3];
        }
        s0 += __shfl_xor_sync(0xffffffff, s0, 1);
        s0 += __shfl_xor_sync(0xffffffff, s0, 2);
        s1 += __shfl_xor_sync(0xffffffff, s1, 1);
        s1 += __shfl_xor_sync(0xffffffff, s1, 2);
        l[0] = l[0] * a0 + s0;
        l[1] = l[1] * a1 + s1;
        #pragma unroll
        for (int f = 0; f < 8; f++) {
            O[f][0] *= a0; O[f][1] *= a0;
            O[f][2] *= a1; O[f][3] *= a1;
        }

        // ---- O += Ph.Vh + Pl.Vh + Ph.Vl ----
        int kr = (lane & 7) + ((lane & 16) ? 8 : 0);
        int nc8 = (lane & 8) ? 8 : 0;
        #pragma unroll
        for (int kc = 0; kc < 8; kc++) {
            uint32_t pha[4], pla[4];
            #pragma unroll
            for (int q = 0; q < 2; q++) {
                int f = kc*2 + q;
                #pragma unroll
                for (int rh = 0; rh < 2; rh++) {
                    float x = S[f][rh*2], y = S[f][rh*2 + 1];
                    bf16 hx = __float2bfloat16_rn(x);
                    bf16 hy = __float2bfloat16_rn(y);
                    float lx = x - __bfloat162float(hx);
                    float ly = y - __bfloat162float(hy);
                    __nv_bfloat162 ph; ph.x = hx; ph.y = hy;
                    pha[q*2 + rh] = *(uint32_t*)&ph;
                    pla[q*2 + rh] = packbf(lx, ly);
                }
            }
            #pragma unroll
            for (int ng2 = 0; ng2 < 4; ng2++) {
                uint32_t va = kb + (uint32_t)(FQL*2 /*skip Kh,Kl*/ * 2 + 0) ;
                va = kb + (uint32_t)( (2*FQL) + (kc*16 + kr) * FPAD + ng2*16 + nc8 ) * 2;
                uint32_t vH[4], vL[4];
                ldsm4t(vH[0], vH[1], vH[2], vH[3], va);
                ldsm4t(vL[0], vL[1], vL[2], vL[3], va + FQL*2);
                #pragma unroll
                for (int sub = 0; sub < 2; sub++) {
                    float* c = O[ng2*2 + sub];
                    uint32_t b0 = sub ? vH[1] : vH[0], b1 = sub ? vH[3] : vH[2];
                    uint32_t l0 = sub ? vL[1] : vL[0], l1 = sub ? vL[3] : vL[2];
                    mma16816(c, pha[0], pha[1], pha[2], pha[3], b0, b1);
                    mma16816(c, pla[0], pla[1], pla[2], pla[3], b0, b1);
                    mma16816(c, pha[0], pha[1], pha[2], pha[3], l0, l1);
                }
            }
        }
        __syncthreads();
    }

    // ---- normalize + split write to as3 ----
    float i0 = 1.f / l[0], i1 = 1.f / l[1];
    int rg0 = grow0 + m0 + r4;
    #pragma unroll
    for (int f = 0; f < 8; f++) {
        int col = h*64 + f*8 + c2;
        float v0 = O[f][0] * i0, v1 = O[f][1] * i0;
        float w0 = O[f][2] * i1, w1 = O[f][3] * i1;
        size_t rS0 = (size_t)rg0 * 1536;
        size_t rS1 = (size_t)(rg0 + 8) * 1536;
        bf16 h0, l0h, h1, l1h;
        split2(v0, h0, l0h); split2(v1, h1, l1h);
        __nv_bfloat162 ph; ph.x = h0; ph.y = h1;
        __nv_bfloat162 pl; pl.x = l0h; pl.y = l1h;
        *(__nv_bfloat162*)&as3[rS0 + col]        = ph;
        *(__nv_bfloat162*)&as3[rS0 + 512 + col]  = pl;
        *(__nv_bfloat162*)&as3[rS0 + 1024 + col] = ph;
        split2(w0, h0, l0h); split2(w1, h1, l1h);
        ph.x = h0; ph.y = h1; pl.x = l0h; pl.y = l1h;
        *(__nv_bfloat162*)&as3[rS1 + col]        = ph;
        *(__nv_bfloat162*)&as3[rS1 + 512 + col]  = pl;
        *(__nv_bfloat162*)&as3[rS1 + 1024 + col] = ph;
    }
}

// ---------------- small kernels --------------------------------------------
__global__ void embed_kernel(const int* __restrict__ idx, const float* __restrict__ tok,
                             const float* __restrict__ pos, float* __restrict__ out) {
    int r = blockIdx.x;
    int t = r & (Td - 1);
    int token = idx[r];
    int c = threadIdx.x;
    const float* tp = tok + (size_t)token * Cd;
    const float* pp = pos + (size_t)t * Cd;
    float* op = out + (size_t)r * Cd;
    op[c] = tp[c] + pp[c];
    op[c + 256] = tp[c + 256] + pp[c + 256];
}

template<bool ADD, bool FOUT>
__global__ void ln_kernel(const float* __restrict__ in, float* __restrict__ out,
                          const float* __restrict__ gw, const float* __restrict__ bw,
                          const float* __restrict__ add, bf16* __restrict__ s3) {
    int r = blockIdx.x;
    const float* x = in + (size_t)r * Cd;
    int tid = threadIdx.x;
    float v0 = x[tid], v1 = x[tid + 256];
    __shared__ float rs[256], rq[256];
    rs[tid] = v0 + v1;
    rq[tid] = v0 * v0 + v1 * v1;
    __syncthreads();
    #pragma unroll
    for (int off = 128; off > 0; off >>= 1) {
        if (tid < off) { rs[tid] += rs[tid+off]; rq[tid] += rq[tid+off]; }
        __syncthreads();
    }
    float mean = rs[0] * (1.0f / Cd);
    float var = rq[0] * (1.0f / Cd) - mean * mean;
    float inv = rsqrtf(var + 1e-5f);
    float o0 = (v0 - mean) * inv * gw[tid] + bw[tid];
    float o1 = (v1 - mean) * inv * gw[tid+256] + bw[tid+256];
    if (ADD) {
        o0 += add[(size_t)r * Cd + tid];
        o1 += add[(size_t)r * Cd + tid + 256];
    }
    if (FOUT) {
        out[(size_t)r * Cd + tid] = o0;
        out[(size_t)r * Cd + tid + 256] = o1;
    }
    bf16 h, l;
    size_t base = (size_t)r * 3 * Cd;
    split2(o0, h, l);
    s3[base + tid] = h; s3[base + Cd + tid] = l; s3[base + 2*Cd + tid] = h;
    split2(o1, h, l);
    s3[base + tid + 256] = h; s3[base + Cd + tid + 256] = l; s3[base + 2*Cd + tid + 256] = h;
}

__global__ void prep_qkv_w(const float* __restrict__ wq, const float* __restrict__ wk,
                           const float* __restrict__ wv, bf16* __restrict__ o3) {
    int i = blockIdx.x * 256 + threadIdx.x;
    if (i >= Ld * QKVW * Cd) return;
    int k = i % Cd;
    int n = (i / Cd) % QKVW;
    int l = i / (Cd * QKVW);
    int which = n >> 9, h = (n >> 6) & 7, d = n & 63;
    const float* src = (which == 0) ? wq : (which == 1) ? wk : wv;
    float v = src[(((size_t)l * Hd + h) * Cd + k) * HSd + d];
    bf16 hh, ll; split2(v, hh, ll);
    size_t base = ((size_t)l * QKVW + n) * 3 * Cd;
    o3[base + k] = hh; o3[base + Cd + k] = hh; o3[base + 2*Cd + k] = ll;
}
__global__ void split_b3(const float* __restrict__ in, bf16* __restrict__ o3,
                         int n, int W) {
    int i = blockIdx.x * 256 + threadIdx.x;
    if (i >= n) return;
    int r = i / W, k = i - r * W;
    bf16 h, l; split2(in[i], h, l);
    size_t base = (size_t)r * 3 * W;
    o3[base + k] = h; o3[base + W + k] = h; o3[base + 2*W + k] = l;
}
__global__ void transpose_b3(const float* __restrict__ in, bf16* __restrict__ o3,
                             int K, int N) {
    __shared__ float tsm[32][33];
    in += (size_t)blockIdx.z * K * N;
    o3 += (size_t)blockIdx.z * N * 3 * K;
    int n0 = blockIdx.x * 32, k0 = blockIdx.y * 32;
    for (int j = threadIdx.y; j < 32; j += 8)
        tsm[j][threadIdx.x] = in[(size_t)(k0 + j) * N + n0 + threadIdx.x];
    __syncthreads();
    for (int i = threadIdx.y; i < 32; i += 8) {
        float v = tsm[threadIdx.x][i];
        bf16 h, l; split2(v, h, l);
        size_t base = (size_t)(n0 + i) * 3 * K;
        int k = k0 + threadIdx.x;
        o3[base + k] = h; o3[base + K + k] = h; o3[base + 2*K + k] = l;
    }
}

// ---------------- host -----------------------------------------------------
extern "C" void kernel_launch(void* const* d_in, const int* in_sizes, int n_in,
                              void* d_out, int out_size) {
    const int*   idx     = (const int*)  d_in[0];
    const float* tok_emb = (const float*)d_in[1];
    const float* pos_emb = (const float*)d_in[2];
    const float* ln1_g   = (const float*)d_in[3];
    const float* ln1_b   = (const float*)d_in[4];
    const float* wq      = (const float*)d_in[5];
    const float* wk      = (const float*)d_in[6];
    const float* wv      = (const float*)d_in[7];
    const float* proj_w  = (const float*)d_in[8];
    const float* proj_b  = (const float*)d_in[9];
    const float* ln2_g   = (const float*)d_in[10];
    const float* ln2_b   = (const float*)d_in[11];
    const float* ff_w1   = (const float*)d_in[12];
    const float* ff_b1   = (const float*)d_in[13];
    const float* ff_w2   = (const float*)d_in[14];
    const float* ff_b2   = (const float*)d_in[15];
    const float* ffln_g  = (const float*)d_in[16];
    const float* ffln_b  = (const float*)d_in[17];
    const float* lm_w    = (const float*)d_in[18];
    const float* lm_b    = (const float*)d_in[19];
    float* out = (float*)d_out;

    float *x, *ff2;
    cudaGetSymbolAddress((void**)&x,   g_x);
    cudaGetSymbolAddress((void**)&ff2, g_ff2);
    bf16 *qkv3, *hs3, *as3, *xs3, *f13, *wqkv3, *wproj3, *wff13, *wff23, *wlm3;
    cudaGetSymbolAddress((void**)&qkv3,  g_qkv3);
    cudaGetSymbolAddress((void**)&hs3,   g_hs3);
    cudaGetSymbolAddress((void**)&as3,   g_as3);
    cudaGetSymbolAddress((void**)&xs3,   g_xs3);
    cudaGetSymbolAddress((void**)&f13,   g_f13);
    cudaGetSymbolAddress((void**)&wqkv3, g_wqkv3);
    cudaGetSymbolAddress((void**)&wproj3,g_wproj3);
    cudaGetSymbolAddress((void**)&wff13, g_wff13);
    cudaGetSymbolAddress((void**)&wff23, g_wff23);
    cudaGetSymbolAddress((void**)&wlm3,  g_wlm3);

    cudaFuncSetAttribute(flash_kernel, cudaFuncAttributeMaxDynamicSharedMemorySize,
                         FLASH_SMEM);

    embed_kernel<<<NT, 256>>>(idx, tok_emb, pos_emb, x);
    prep_qkv_w<<<(Ld*QKVW*Cd + 255)/256, 256>>>(wq, wk, wv, wqkv3);
    split_b3<<<(Ld*Cd*Cd + 255)/256, 256>>>(proj_w, wproj3, Ld*Cd*Cd, Cd);
    transpose_b3<<<dim3(FFW/32, Cd/32, Ld), dim3(32,8)>>>(ff_w1, wff13, Cd, FFW);
    transpose_b3<<<dim3(Cd/32, FFW/32, Ld), dim3(32,8)>>>(ff_w2, wff23, FFW, Cd);
    transpose_b3<<<dim3(Vd/32, Cd/32, 1),  dim3(32,8)>>>(lm_w, wlm3, Cd, Vd);

    for (int l = 0; l < Ld; l++) {
        ln_kernel<false,false><<<NT, 256>>>(x, nullptr, ln1_g + l*Cd, ln1_b + l*Cd,
                                            nullptr, hs3);
        // QKV -> split bf16 directly
        hgemm<false,false,false,false,true><<<dim3(NT/128, QKVW/128), 256>>>(
            hs3, wqkv3 + (size_t)l*QKVW*3*Cd, nullptr, nullptr, nullptr, qkv3,
            NT, QKVW, 3*Cd);
        // fused flash attention -> as3 (split)
        flash_kernel<<<dim3(Td/128, Bd*Hd), 256, FLASH_SMEM>>>(qkv3, as3);
        // proj + bias + residual -> x
        hgemm<true,false,true,true,false><<<dim3(NT/128, Cd/128), 256>>>(
            as3, wproj3 + (size_t)l*Cd*3*Cd, x, proj_b + l*Cd, x, nullptr,
            NT, Cd, 3*Cd);
        ln_kernel<false,false><<<NT, 256>>>(x, nullptr, ln2_g + l*Cd, ln2_b + l*Cd,
                                            nullptr, hs3);
        hgemm<true,true,false,false,true><<<dim3(NT/128, FFW/128), 256>>>(
            hs3, wff13 + (size_t)l*FFW*3*Cd, nullptr, ff_b1 + l*FFW, nullptr, f13,
            NT, FFW, 3*Cd);
        hgemm<true,false,false,true,false><<<dim3(NT/128, Cd/128), 256>>>(
            f13, wff23 + (size_t)l*Cd*3*FFW, ff2, ff_b2 + l*Cd, nullptr, nullptr,
            NT, Cd, 3*FFW);
        ln_kernel<true,true><<<NT, 256>>>(ff2, x, ffln_g + l*Cd, ffln_b + l*Cd,
                                          x, xs3);
    }
    hgemm<true,false,false,true,false><<<dim3(NT/128, Vd/128), 256>>>(
        xs3, wlm3, out, lm_b, nullptr, nullptr, NT, Vd, 3*Cd);
}

// round 9
// speedup vs baseline: 2.6620x; 1.1035x over previous
#include <cuda_runtime.h>
#include <cuda_bf16.h>
#include <cstdint>

#define Bd 2
#define Td 2048
#define Cd 512
#define Hd 8
#define HSd 64
#define Ld 4
#define Vd 32000
#define NT (Bd*Td)
#define QKVW (3*Cd)
#define FFW (4*Cd)
#define QKV3W (3*QKVW)       // 4608

typedef __nv_bfloat16 bf16;

// ---------------- scratch --------------------------------------------------
__device__ float g_x   [NT*Cd];
__device__ float g_ff2 [NT*Cd];
__device__ bf16 g_qkv3[(size_t)NT*QKV3W];      // [Qh Kh Vh | Ql Kl Vl | Qh Kh Vh]
__device__ bf16 g_hs3 [NT*3*Cd];
__device__ bf16 g_as3 [NT*3*Cd];
__device__ bf16 g_xs3 [NT*3*Cd];
__device__ bf16 g_f13 [NT*3*FFW];
__device__ bf16 g_wqkv3 [Ld*QKVW*3*Cd];
__device__ bf16 g_wproj3[Ld*Cd*3*Cd];
__device__ bf16 g_wff13 [Ld*FFW*3*Cd];
__device__ bf16 g_wff23 [Ld*Cd*3*FFW];
__device__ bf16 g_wlm3  [(size_t)Vd*3*Cd];

// ---------------- helpers --------------------------------------------------
__device__ __forceinline__ uint32_t smem_u32(const void* p) {
    uint32_t a;
    asm("{ .reg .u64 t; cvta.to.shared.u64 t, %1; cvt.u32.u64 %0, t; }" : "=r"(a) : "l"(p));
    return a;
}
__device__ __forceinline__ void cp16(uint32_t d, const void* s) {
    asm volatile("cp.async.cg.shared.global [%0], [%1], 16;" :: "r"(d), "l"(s));
}
#define CP_COMMIT() asm volatile("cp.async.commit_group;" ::: "memory")
template<int N> __device__ __forceinline__ void cp_wait() {
    asm volatile("cp.async.wait_group %0;" :: "n"(N) : "memory");
}
__device__ __forceinline__ void ldsm4(uint32_t& r0, uint32_t& r1, uint32_t& r2,
                                      uint32_t& r3, uint32_t addr) {
    asm volatile("ldmatrix.sync.aligned.m8n8.x4.shared.b16 {%0,%1,%2,%3}, [%4];"
                 : "=r"(r0), "=r"(r1), "=r"(r2), "=r"(r3) : "r"(addr));
}
__device__ __forceinline__ void ldsm4t(uint32_t& r0, uint32_t& r1, uint32_t& r2,
                                       uint32_t& r3, uint32_t addr) {
    asm volatile("ldmatrix.sync.aligned.m8n8.x4.trans.shared.b16 {%0,%1,%2,%3}, [%4];"
                 : "=r"(r0), "=r"(r1), "=r"(r2), "=r"(r3) : "r"(addr));
}
__device__ __forceinline__ void mma16816(float* c, uint32_t a0, uint32_t a1,
                                         uint32_t a2, uint32_t a3,
                                         uint32_t b0, uint32_t b1) {
    asm volatile(
        "mma.sync.aligned.m16n8k16.row.col.f32.bf16.bf16.f32 "
        "{%0,%1,%2,%3}, {%4,%5,%6,%7}, {%8,%9}, {%0,%1,%2,%3};"
        : "+f"(c[0]), "+f"(c[1]), "+f"(c[2]), "+f"(c[3])
        : "r"(a0), "r"(a1), "r"(a2), "r"(a3), "r"(b0), "r"(b1));
}
__device__ __forceinline__ void split2(float v, bf16& h, bf16& l) {
    h = __float2bfloat16_rn(v);
    l = __float2bfloat16_rn(v - __bfloat162float(h));
}
__device__ __forceinline__ uint32_t packbf(float x, float y) {
    __nv_bfloat162 t = __floats2bfloat162_rn(x, y);
    return *(uint32_t*)&t;
}

// ---------------- HMMA GEMM: C[M,N] = A3[M,K3] . B3[N,K3]^T ---------------
// MI=4: 128x128 tile (8 warps, warp 64x32). MI=2: 64x128 tile (warp 32x32).
// 2 CTAs/SM co-residency for latency hiding across cp_wait/syncthreads.
#define SSTRIDE 40

template<int MI, bool BIAS, bool RELU, bool RESID, bool COUT, bool SPLITOUT>
__global__ void __launch_bounds__(256, 2)
hgemm(const bf16* __restrict__ A3, const bf16* __restrict__ B3,
      float* __restrict__ C, const float* __restrict__ bias,
      const float* __restrict__ resid, bf16* __restrict__ S3,
      int M, int N, int K3) {
    constexpr int AROWS = MI * 32;
    __shared__ bf16 As[2][AROWS * SSTRIDE];
    __shared__ bf16 Bs[2][128 * SSTRIDE];
    int tid = threadIdx.x;
    int row0 = blockIdx.x * AROWS;
    int col0 = blockIdx.y * 128;
    int lane = tid & 31, wid = tid >> 5;
    int m0 = (wid & 1) * (MI * 16), n0 = (wid >> 1) * 32;

    int lrow = tid >> 2;
    int lcol = (tid & 3) * 8;
    const bf16* pA0 = A3 + (size_t)(row0 + lrow) * K3 + lcol;
    const bf16* pA1 = A3 + (size_t)(row0 + lrow + 64) * K3 + lcol;
    const bf16* pB0 = B3 + (size_t)(col0 + lrow) * K3 + lcol;
    const bf16* pB1 = B3 + (size_t)(col0 + lrow + 64) * K3 + lcol;
    uint32_t sA = smem_u32(As), sB = smem_u32(Bs);
    uint32_t stA0 = sA + (uint32_t)(lrow*SSTRIDE + lcol)*2;
    uint32_t stA1 = sA + (uint32_t)((lrow+64)*SSTRIDE + lcol)*2;
    uint32_t stB0 = sB + (uint32_t)(lrow*SSTRIDE + lcol)*2;
    uint32_t stB1 = sB + (uint32_t)((lrow+64)*SSTRIDE + lcol)*2;
    const uint32_t stageA = AROWS * SSTRIDE * 2;
    const uint32_t stageB = 128 * SSTRIDE * 2;

    float acc[MI][4][4];
    #pragma unroll
    for (int i = 0; i < MI; i++)
        #pragma unroll
        for (int j = 0; j < 4; j++)
            #pragma unroll
            for (int q = 0; q < 4; q++) acc[i][j][q] = 0.0f;

    int NIT = K3 >> 5;
    cp16(stA0, pA0);
    if (MI == 4) cp16(stA1, pA1);
    cp16(stB0, pB0); cp16(stB1, pB1);
    CP_COMMIT();

    uint32_t aoff = (uint32_t)((m0 + (lane & 15)) * SSTRIDE + (lane >> 4) * 8) * 2;
    uint32_t boff = (uint32_t)((n0 + (lane & 15)) * SSTRIDE + (lane >> 4) * 8) * 2;

    for (int it = 0; it < NIT; it++) {
        int sc = it & 1;
        if (it + 1 < NIT) {
            uint32_t soA = (uint32_t)((it + 1) & 1) * stageA;
            uint32_t soB = (uint32_t)((it + 1) & 1) * stageB;
            int ko = (it + 1) << 5;
            cp16(stA0 + soA, pA0 + ko);
            if (MI == 4) cp16(stA1 + soA, pA1 + ko);
            cp16(stB0 + soB, pB0 + ko); cp16(stB1 + soB, pB1 + ko);
            CP_COMMIT();
            cp_wait<1>();
        } else {
            cp_wait<0>();
        }
        __syncthreads();
        uint32_t sa = sA + (uint32_t)sc * stageA + aoff;
        uint32_t sb = sB + (uint32_t)sc * stageB + boff;
        #pragma unroll
        for (int kk = 0; kk < 2; kk++) {
            uint32_t a[MI][4], b[2][4];
            #pragma unroll
            for (int mi = 0; mi < MI; mi++)
                ldsm4(a[mi][0], a[mi][1], a[mi][2], a[mi][3],
                      sa + (uint32_t)(mi*16*SSTRIDE + kk*16)*2);
            #pragma unroll
            for (int nj = 0; nj < 2; nj++)
                ldsm4(b[nj][0], b[nj][1], b[nj][2], b[nj][3],
                      sb + (uint32_t)(nj*16*SSTRIDE + kk*16)*2);
            #pragma unroll
            for (int mi = 0; mi < MI; mi++) {
                #pragma unroll
                for (int ni = 0; ni < 4; ni++) {
                    int nj = ni >> 1, sub = ni & 1;
                    mma16816(acc[mi][ni], a[mi][0], a[mi][1], a[mi][2], a[mi][3],
                             sub ? b[nj][1] : b[nj][0],
                             sub ? b[nj][3] : b[nj][2]);
                }
            }
        }
        __syncthreads();
    }

    int r4 = lane >> 2, c2 = (lane & 3) * 2;
    #pragma unroll
    for (int mi = 0; mi < MI; mi++) {
        #pragma unroll
        for (int half = 0; half < 2; half++) {
            int row = row0 + m0 + mi*16 + r4 + half*8;
            size_t rowN = (size_t)row * N;
            size_t rowS = (size_t)row * 3 * N;
            #pragma unroll
            for (int ni = 0; ni < 4; ni++) {
                int col = col0 + n0 + ni*8 + c2;
                float v0 = acc[mi][ni][half*2 + 0];
                float v1 = acc[mi][ni][half*2 + 1];
                if (BIAS) { v0 += bias[col]; v1 += bias[col + 1]; }
                if (RESID) {
                    float2 rv = *(const float2*)&resid[rowN + col];
                    v0 += rv.x; v1 += rv.y;
                }
                if (RELU) { v0 = fmaxf(v0, 0.f); v1 = fmaxf(v1, 0.f); }
                if (COUT) *(float2*)&C[rowN + col] = make_float2(v0, v1);
                if (SPLITOUT) {
                    bf16 h0, l0, h1, l1;
                    split2(v0, h0, l0); split2(v1, h1, l1);
                    __nv_bfloat162 ph; ph.x = h0; ph.y = h1;
                    __nv_bfloat162 pl; pl.x = l0; pl.y = l1;
                    *(__nv_bfloat162*)&S3[rowS + col]       = ph;
                    *(__nv_bfloat162*)&S3[rowS + N + col]   = pl;
                    *(__nv_bfloat162*)&S3[rowS + 2*N + col] = ph;
                }
            }
        }
    }
}

// ---------------- flash attention ------------------------------------------
// 1D grid (256), heavy q-tiles first for causal load balance.
#define FPAD 72
#define FQL 9216
#define FKV 18432
#define FSTG 36864
#define FLASH_SMEM ((FKV + 2*FSTG) * 2)

__global__ void __launch_bounds__(256, 1)
flash_kernel(const bf16* __restrict__ qkv3, bf16* __restrict__ as3) {
    extern __shared__ bf16 fsm[];
    uint32_t sbase = smem_u32(fsm);
    int tid = threadIdx.x, lane = tid & 31, wid = tid >> 5;
    int z = blockIdx.x;
    int qt = 15 - (z >> 4);          // heavy tiles first
    int bh = z & 15;
    int b = bh >> 3, h = bh & 7;
    int grow0 = b * Td + qt * 128;
    int m0 = wid * 16;

    int r2 = tid >> 1, c32 = (tid & 1) * 32;
    {   // Q (hi at col h*64, lo at 1536+h*64)
        const bf16* src = qkv3 + (size_t)(grow0 + r2) * QKV3W + c32;
        uint32_t d = sbase + (uint32_t)(r2 * FPAD + c32) * 2;
        #pragma unroll
        for (int j = 0; j < 4; j++) {
            cp16(d + j*16,           src + h*64 + j*8);
            cp16(d + FQL*2 + j*16,   src + 1536 + h*64 + j*8);
        }
    }
    auto load_kv = [&](int stage, int kv) {
        const bf16* src = qkv3 + (size_t)(b * Td + kv * 128 + r2) * QKV3W + c32;
        uint32_t d = sbase + (uint32_t)(FKV + stage*FSTG + r2 * FPAD + c32) * 2;
        #pragma unroll
        for (int j = 0; j < 4; j++) {
            cp16(d + j*16,            src + 512 + h*64 + j*8);         // Kh
            cp16(d + FQL*2 + j*16,    src + 1536 + 512 + h*64 + j*8);  // Kl
            cp16(d + FQL*4 + j*16,    src + 1024 + h*64 + j*8);        // Vh
            cp16(d + FQL*6 + j*16,    src + 1536 + 1024 + h*64 + j*8); // Vl
        }
    };
    load_kv(0, 0);
    CP_COMMIT();

    float m[2] = {-1e30f, -1e30f}, l[2] = {0.f, 0.f};
    float O[8][4];
    #pragma unroll
    for (int f = 0; f < 8; f++)
        #pragma unroll
        for (int e = 0; e < 4; e++) O[f][e] = 0.f;

    int nkv = qt + 1;
    int r4 = lane >> 2, c2 = (lane & 3) * 2;
    int rowg0 = qt*128 + m0 + r4;

    for (int kv = 0; kv < nkv; kv++) {
        if (kv + 1 < nkv) { load_kv((kv + 1) & 1, kv + 1); CP_COMMIT(); cp_wait<1>(); }
        else cp_wait<0>();
        __syncthreads();
        uint32_t kb = sbase + (uint32_t)(FKV + (kv & 1) * FSTG) * 2;

        float S[16][4];
        #pragma unroll
        for (int f = 0; f < 16; f++)
            #pragma unroll
            for (int e = 0; e < 4; e++) S[f][e] = 0.f;
        #pragma unroll
        for (int kc = 0; kc < 4; kc++) {
            uint32_t qa = sbase + (uint32_t)((m0 + (lane & 15)) * FPAD + kc*16 + (lane >> 4)*8) * 2;
            uint32_t aH[4], aL[4];
            ldsm4(aH[0], aH[1], aH[2], aH[3], qa);
            ldsm4(aL[0], aL[1], aL[2], aL[3], qa + FQL*2);
            #pragma unroll
            for (int ng = 0; ng < 8; ng++) {
                uint32_t ka = kb + (uint32_t)((ng*16 + (lane & 15)) * FPAD + kc*16 + (lane >> 4)*8) * 2;
                uint32_t bH[4], bL[4];
                ldsm4(bH[0], bH[1], bH[2], bH[3], ka);
                ldsm4(bL[0], bL[1], bL[2], bL[3], ka + FQL*2);
                #pragma unroll
                for (int sub = 0; sub < 2; sub++) {
                    float* c = S[ng*2 + sub];
                    uint32_t b0 = sub ? bH[1] : bH[0], b1 = sub ? bH[3] : bH[2];
                    uint32_t l0 = sub ? bL[1] : bL[0], l1 = sub ? bL[3] : bL[2];
                    mma16816(c, aH[0], aH[1], aH[2], aH[3], b0, b1);
                    mma16816(c, aL[0], aL[1], aL[2], aL[3], b0, b1);
                    mma16816(c, aH[0], aH[1], aH[2], aH[3], l0, l1);
                }
            }
        }

        if (kv == qt) {
            #pragma unroll
            for (int f = 0; f < 16; f++) {
                int colb = kv*128 + f*8 + c2;
                #pragma unroll
                for (int e = 0; e < 4; e++) {
                    int col = colb + (e & 1);
                    int row = rowg0 + ((e & 2) ? 8 : 0);
                    if (col > row) S[f][e] = -1e30f;
                }
            }
        }

        float mx0 = -1e30f, mx1 = -1e30f;
        #pragma unroll
        for (int f = 0; f < 16; f++) {
            mx0 = fmaxf(mx0, fmaxf(S[f][0], S[f][1]));
            mx1 = fmaxf(mx1, fmaxf(S[f][2], S[f][3]));
        }
        mx0 = fmaxf(mx0, __shfl_xor_sync(0xffffffff, mx0, 1));
        mx0 = fmaxf(mx0, __shfl_xor_sync(0xffffffff, mx0, 2));
        mx1 = fmaxf(mx1, __shfl_xor_sync(0xffffffff, mx1, 1));
        mx1 = fmaxf(mx1, __shfl_xor_sync(0xffffffff, mx1, 2));
        float mn0 = fmaxf(m[0], mx0), mn1 = fmaxf(m[1], mx1);
        float a0 = __expf(m[0] - mn0), a1 = __expf(m[1] - mn1);
        m[0] = mn0; m[1] = mn1;
        float s0 = 0.f, s1 = 0.f;
        #pragma unroll
        for (int f = 0; f < 16; f++) {
            S[f][0] = __expf(S[f][0] - mn0);
            S[f][1] = __expf(S[f][1] - mn0);
            S[f][2] = __expf(S[f][2] - mn1);
            S[f][3] = __expf(S[f][3] - mn1);
            s0 += S[f][0] + S[f][1];
            s1 += S[f][2] + S[f][3];
        }
        s0 += __shfl_xor_sync(0xffffffff, s0, 1);
        s0 += __shfl_xor_sync(0xffffffff, s0, 2);
        s1 += __shfl_xor_sync(0xffffffff, s1, 1);
        s1 += __shfl_xor_sync(0xffffffff, s1, 2);
        l[0] = l[0] * a0 + s0;
        l[1] = l[1] * a1 + s1;
        #pragma unroll
        for (int f = 0; f < 8; f++) {
            O[f][0] *= a0; O[f][1] *= a0;
            O[f][2] *= a1; O[f][3] *= a1;
        }

        int kr = (lane & 7) + ((lane & 16) ? 8 : 0);
        int nc8 = (lane & 8) ? 8 : 0;
        #pragma unroll
        for (int kc = 0; kc < 8; kc++) {
            uint32_t pha[4], pla[4];
            #pragma unroll
            for (int q = 0; q < 2; q++) {
                int f = kc*2 + q;
                #pragma unroll
                for (int rh = 0; rh < 2; rh++) {
                    float x = S[f][rh*2], y = S[f][rh*2 + 1];
                    bf16 hx = __float2bfloat16_rn(x);
                    bf16 hy = __float2bfloat16_rn(y);
                    float lx = x - __bfloat162float(hx);
                    float ly = y - __bfloat162float(hy);
                    __nv_bfloat162 ph; ph.x = hx; ph.y = hy;
                    pha[q*2 + rh] = *(uint32_t*)&ph;
                    pla[q*2 + rh] = packbf(lx, ly);
                }
            }
            #pragma unroll
            for (int ng2 = 0; ng2 < 4; ng2++) {
                uint32_t va = kb + (uint32_t)((2*FQL) + (kc*16 + kr) * FPAD + ng2*16 + nc8) * 2;
                uint32_t vH[4], vL[4];
                ldsm4t(vH[0], vH[1], vH[2], vH[3], va);
                ldsm4t(vL[0], vL[1], vL[2], vL[3], va + FQL*2);
                #pragma unroll
                for (int sub = 0; sub < 2; sub++) {
                    float* c = O[ng2*2 + sub];
                    uint32_t b0 = sub ? vH[1] : vH[0], b1 = sub ? vH[3] : vH[2];
                    uint32_t l0 = sub ? vL[1] : vL[0], l1 = sub ? vL[3] : vL[2];
                    mma16816(c, pha[0], pha[1], pha[2], pha[3], b0, b1);
                    mma16816(c, pla[0], pla[1], pla[2], pla[3], b0, b1);
                    mma16816(c, pha[0], pha[1], pha[2], pha[3], l0, l1);
                }
            }
        }
        __syncthreads();
    }

    float i0 = 1.f / l[0], i1 = 1.f / l[1];
    int rg0 = grow0 + m0 + r4;
    #pragma unroll
    for (int f = 0; f < 8; f++) {
        int col = h*64 + f*8 + c2;
        float v0 = O[f][0] * i0, v1 = O[f][1] * i0;
        float w0 = O[f][2] * i1, w1 = O[f][3] * i1;
        size_t rS0 = (size_t)rg0 * 1536;
        size_t rS1 = (size_t)(rg0 + 8) * 1536;
        bf16 h0, l0h, h1, l1h;
        split2(v0, h0, l0h); split2(v1, h1, l1h);
        __nv_bfloat162 ph; ph.x = h0; ph.y = h1;
        __nv_bfloat162 pl; pl.x = l0h; pl.y = l1h;
        *(__nv_bfloat162*)&as3[rS0 + col]        = ph;
        *(__nv_bfloat162*)&as3[rS0 + 512 + col]  = pl;
        *(__nv_bfloat162*)&as3[rS0 + 1024 + col] = ph;
        split2(w0, h0, l0h); split2(w1, h1, l1h);
        ph.x = h0; ph.y = h1; pl.x = l0h; pl.y = l1h;
        *(__nv_bfloat162*)&as3[rS1 + col]        = ph;
        *(__nv_bfloat162*)&as3[rS1 + 512 + col]  = pl;
        *(__nv_bfloat162*)&as3[rS1 + 1024 + col] = ph;
    }
}

// ---------------- small kernels --------------------------------------------
__global__ void embed_kernel(const int* __restrict__ idx, const float* __restrict__ tok,
                             const float* __restrict__ pos, float* __restrict__ out) {
    int r = blockIdx.x;
    int t = r & (Td - 1);
    int token = idx[r];
    int c = threadIdx.x;
    const float* tp = tok + (size_t)token * Cd;
    const float* pp = pos + (size_t)t * Cd;
    float* op = out + (size_t)r * Cd;
    op[c] = tp[c] + pp[c];
    op[c + 256] = tp[c + 256] + pp[c + 256];
}

template<bool ADD, bool FOUT>
__global__ void ln_kernel(const float* __restrict__ in, float* __restrict__ out,
                          const float* __restrict__ gw, const float* __restrict__ bw,
                          const float* __restrict__ add, bf16* __restrict__ s3) {
    int r = blockIdx.x;
    const float* x = in + (size_t)r * Cd;
    int tid = threadIdx.x;
    float v0 = x[tid], v1 = x[tid + 256];
    __shared__ float rs[256], rq[256];
    rs[tid] = v0 + v1;
    rq[tid] = v0 * v0 + v1 * v1;
    __syncthreads();
    #pragma unroll
    for (int off = 128; off > 0; off >>= 1) {
        if (tid < off) { rs[tid] += rs[tid+off]; rq[tid] += rq[tid+off]; }
        __syncthreads();
    }
    float mean = rs[0] * (1.0f / Cd);
    float var = rq[0] * (1.0f / Cd) - mean * mean;
    float inv = rsqrtf(var + 1e-5f);
    float o0 = (v0 - mean) * inv * gw[tid] + bw[tid];
    float o1 = (v1 - mean) * inv * gw[tid+256] + bw[tid+256];
    if (ADD) {
        o0 += add[(size_t)r * Cd + tid];
        o1 += add[(size_t)r * Cd + tid + 256];
    }
    if (FOUT) {
        out[(size_t)r * Cd + tid] = o0;
        out[(size_t)r * Cd + tid + 256] = o1;
    }
    bf16 h, l;
    size_t base = (size_t)r * 3 * Cd;
    split2(o0, h, l);
    s3[base + tid] = h; s3[base + Cd + tid] = l; s3[base + 2*Cd + tid] = h;
    split2(o1, h, l);
    s3[base + tid + 256] = h; s3[base + Cd + tid + 256] = l; s3[base + 2*Cd + tid + 256] = h;
}

__global__ void prep_qkv_w(const float* __restrict__ wq, const float* __restrict__ wk,
                           const float* __restrict__ wv, bf16* __restrict__ o3) {
    int i = blockIdx.x * 256 + threadIdx.x;
    if (i >= Ld * QKVW * Cd) return;
    int k = i % Cd;
    int n = (i / Cd) % QKVW;
    int l = i / (Cd * QKVW);
    int which = n >> 9, h = (n >> 6) & 7, d = n & 63;
    const float* src = (which == 0) ? wq : (which == 1) ? wk : wv;
    float v = src[(((size_t)l * Hd + h) * Cd + k) * HSd + d];
    bf16 hh, ll; split2(v, hh, ll);
    size_t base = ((size_t)l * QKVW + n) * 3 * Cd;
    o3[base + k] = hh; o3[base + Cd + k] = hh; o3[base + 2*Cd + k] = ll;
}
__global__ void split_b3(const float* __restrict__ in, bf16* __restrict__ o3,
                         int n, int W) {
    int i = blockIdx.x * 256 + threadIdx.x;
    if (i >= n) return;
    int r = i / W, k = i - r * W;
    bf16 h, l; split2(in[i], h, l);
    size_t base = (size_t)r * 3 * W;
    o3[base + k] = h; o3[base + W + k] = h; o3[base + 2*W + k] = l;
}
__global__ void transpose_b3(const float* __restrict__ in, bf16* __restrict__ o3,
                             int K, int N) {
    __shared__ float tsm[32][33];
    in += (size_t)blockIdx.z * K * N;
    o3 += (size_t)blockIdx.z * N * 3 * K;
    int n0 = blockIdx.x * 32, k0 = blockIdx.y * 32;
    for (int j = threadIdx.y; j < 32; j += 8)
        tsm[j][threadIdx.x] = in[(size_t)(k0 + j) * N + n0 + threadIdx.x];
    __syncthreads();
    for (int i = threadIdx.y; i < 32; i += 8) {
        float v = tsm[threadIdx.x][i];
        bf16 h, l; split2(v, h, l);
        size_t base = (size_t)(n0 + i) * 3 * K;
        int k = k0 + threadIdx.x;
        o3[base + k] = h; o3[base + K + k] = h; o3[base + 2*K + k] = l;
    }
}

// ---------------- host -----------------------------------------------------
extern "C" void kernel_launch(void* const* d_in, const int* in_sizes, int n_in,
                              void* d_out, int out_size) {
    const int*   idx     = (const int*)  d_in[0];
    const float* tok_emb = (const float*)d_in[1];
    const float* pos_emb = (const float*)d_in[2];
    const float* ln1_g   = (const float*)d_in[3];
    const float* ln1_b   = (const float*)d_in[4];
    const float* wq      = (const float*)d_in[5];
    const float* wk      = (const float*)d_in[6];
    const float* wv      = (const float*)d_in[7];
    const float* proj_w  = (const float*)d_in[8];
    const float* proj_b  = (const float*)d_in[9];
    const float* ln2_g   = (const float*)d_in[10];
    const float* ln2_b   = (const float*)d_in[11];
    const float* ff_w1   = (const float*)d_in[12];
    const float* ff_b1   = (const float*)d_in[13];
    const float* ff_w2   = (const float*)d_in[14];
    const float* ff_b2   = (const float*)d_in[15];
    const float* ffln_g  = (const float*)d_in[16];
    const float* ffln_b  = (const float*)d_in[17];
    const float* lm_w    = (const float*)d_in[18];
    const float* lm_b    = (const float*)d_in[19];
    float* out = (float*)d_out;

    float *x, *ff2;
    cudaGetSymbolAddress((void**)&x,   g_x);
    cudaGetSymbolAddress((void**)&ff2, g_ff2);
    bf16 *qkv3, *hs3, *as3, *xs3, *f13, *wqkv3, *wproj3, *wff13, *wff23, *wlm3;
    cudaGetSymbolAddress((void**)&qkv3,  g_qkv3);
    cudaGetSymbolAddress((void**)&hs3,   g_hs3);
    cudaGetSymbolAddress((void**)&as3,   g_as3);
    cudaGetSymbolAddress((void**)&xs3,   g_xs3);
    cudaGetSymbolAddress((void**)&f13,   g_f13);
    cudaGetSymbolAddress((void**)&wqkv3, g_wqkv3);
    cudaGetSymbolAddress((void**)&wproj3,g_wproj3);
    cudaGetSymbolAddress((void**)&wff13, g_wff13);
    cudaGetSymbolAddress((void**)&wff23, g_wff23);
    cudaGetSymbolAddress((void**)&wlm3,  g_wlm3);

    cudaFuncSetAttribute(flash_kernel, cudaFuncAttributeMaxDynamicSharedMemorySize,
                         FLASH_SMEM);

    embed_kernel<<<NT, 256>>>(idx, tok_emb, pos_emb, x);
    prep_qkv_w<<<(Ld*QKVW*Cd + 255)/256, 256>>>(wq, wk, wv, wqkv3);
    split_b3<<<(Ld*Cd*Cd + 255)/256, 256>>>(proj_w, wproj3, Ld*Cd*Cd, Cd);
    transpose_b3<<<dim3(FFW/32, Cd/32, Ld), dim3(32,8)>>>(ff_w1, wff13, Cd, FFW);
    transpose_b3<<<dim3(Cd/32, FFW/32, Ld), dim3(32,8)>>>(ff_w2, wff23, FFW, Cd);
    transpose_b3<<<dim3(Vd/32, Cd/32, 1),  dim3(32,8)>>>(lm_w, wlm3, Cd, Vd);

    for (int l = 0; l < Ld; l++) {
        ln_kernel<false,false><<<NT, 256>>>(x, nullptr, ln1_g + l*Cd, ln1_b + l*Cd,
                                            nullptr, hs3);
        // QKV -> split bf16 directly
        hgemm<4,false,false,false,false,true><<<dim3(NT/128, QKVW/128), 256>>>(
            hs3, wqkv3 + (size_t)l*QKVW*3*Cd, nullptr, nullptr, nullptr, qkv3,
            NT, QKVW, 3*Cd);
        // fused flash attention -> as3 (split), heavy tiles first
        flash_kernel<<<256, 256, FLASH_SMEM>>>(qkv3, as3);
        // proj + bias + residual -> x  (64-row tiles: 256 CTAs)
        hgemm<2,true,false,true,true,false><<<dim3(NT/64, Cd/128), 256>>>(
            as3, wproj3 + (size_t)l*Cd*3*Cd, x, proj_b + l*Cd, x, nullptr,
            NT, Cd, 3*Cd);
        ln_kernel<false,false><<<NT, 256>>>(x, nullptr, ln2_g + l*Cd, ln2_b + l*Cd,
                                            nullptr, hs3);
        hgemm<4,true,true,false,false,true><<<dim3(NT/128, FFW/128), 256>>>(
            hs3, wff13 + (size_t)l*FFW*3*Cd, nullptr, ff_b1 + l*FFW, nullptr, f13,
            NT, FFW, 3*Cd);
        hgemm<2,true,false,false,true,false><<<dim3(NT/64, Cd/128), 256>>>(
            f13, wff23 + (size_t)l*Cd*3*FFW, ff2, ff_b2 + l*Cd, nullptr, nullptr,
            NT, Cd, 3*FFW);
        ln_kernel<true,true><<<NT, 256>>>(ff2, x, ffln_g + l*Cd, ffln_b + l*Cd,
                                          x, xs3);
    }
    hgemm<4,true,false,false,true,false><<<dim3(NT/128, Vd/128), 256>>>(
        xs3, wlm3, out, lm_b, nullptr, nullptr, NT, Vd, 3*Cd);
}

// round 10
// speedup vs baseline: 3.0284x; 1.1377x over previous
#include <cuda_runtime.h>
#include <cuda_bf16.h>
#include <cstdint>

#define Bd 2
#define Td 2048
#define Cd 512
#define Hd 8
#define HSd 64
#define Ld 4
#define Vd 32000
#define NT (Bd*Td)
#define QKVW (3*Cd)
#define FFW (4*Cd)
#define QKV2W (2*QKVW)       // 3072

typedef __nv_bfloat16 bf16;

// ---------------- scratch --------------------------------------------------
__device__ float g_x   [NT*Cd];
__device__ float g_ff2 [NT*Cd];
__device__ bf16 g_qkv2[(size_t)NT*QKV2W];      // [Qh Kh Vh | Ql Kl Vl]
__device__ bf16 g_hs2 [NT*2*Cd];
__device__ bf16 g_as2 [NT*2*Cd];
__device__ bf16 g_xs2 [NT*2*Cd];
__device__ bf16 g_f12 [NT*2*FFW];
__device__ bf16 g_wqkv2 [Ld*QKVW*2*Cd];
__device__ bf16 g_wproj2[Ld*Cd*2*Cd];
__device__ bf16 g_wff12 [Ld*FFW*2*Cd];
__device__ bf16 g_wff22 [Ld*Cd*2*FFW];
__device__ bf16 g_wlm2  [(size_t)Vd*2*Cd];

// ---------------- helpers --------------------------------------------------
__device__ __forceinline__ uint32_t smem_u32(const void* p) {
    uint32_t a;
    asm("{ .reg .u64 t; cvta.to.shared.u64 t, %1; cvt.u32.u64 %0, t; }" : "=r"(a) : "l"(p));
    return a;
}
__device__ __forceinline__ void cp16(uint32_t d, const void* s) {
    asm volatile("cp.async.cg.shared.global [%0], [%1], 16;" :: "r"(d), "l"(s));
}
#define CP_COMMIT() asm volatile("cp.async.commit_group;" ::: "memory")
template<int N> __device__ __forceinline__ void cp_wait() {
    asm volatile("cp.async.wait_group %0;" :: "n"(N) : "memory");
}
__device__ __forceinline__ void ldsm4(uint32_t& r0, uint32_t& r1, uint32_t& r2,
                                      uint32_t& r3, uint32_t addr) {
    asm volatile("ldmatrix.sync.aligned.m8n8.x4.shared.b16 {%0,%1,%2,%3}, [%4];"
                 : "=r"(r0), "=r"(r1), "=r"(r2), "=r"(r3) : "r"(addr));
}
__device__ __forceinline__ void ldsm4t(uint32_t& r0, uint32_t& r1, uint32_t& r2,
                                       uint32_t& r3, uint32_t addr) {
    asm volatile("ldmatrix.sync.aligned.m8n8.x4.trans.shared.b16 {%0,%1,%2,%3}, [%4];"
                 : "=r"(r0), "=r"(r1), "=r"(r2), "=r"(r3) : "r"(addr));
}
__device__ __forceinline__ void mma16816(float* c, uint32_t a0, uint32_t a1,
                                         uint32_t a2, uint32_t a3,
                                         uint32_t b0, uint32_t b1) {
    asm volatile(
        "mma.sync.aligned.m16n8k16.row.col.f32.bf16.bf16.f32 "
        "{%0,%1,%2,%3}, {%4,%5,%6,%7}, {%8,%9}, {%0,%1,%2,%3};"
        : "+f"(c[0]), "+f"(c[1]), "+f"(c[2]), "+f"(c[3])
        : "r"(a0), "r"(a1), "r"(a2), "r"(a3), "r"(b0), "r"(b1));
}
__device__ __forceinline__ void split2(float v, bf16& h, bf16& l) {
    h = __float2bfloat16_rn(v);
    l = __float2bfloat16_rn(v - __bfloat162float(h));
}
__device__ __forceinline__ uint32_t packbf(float x, float y) {
    __nv_bfloat162 t = __floats2bfloat162_rn(x, y);
    return *(uint32_t*)&t;
}

// ---------------- combo HMMA GEMM ------------------------------------------
// C[M,N] = (Ah+Al)[M,K].(Bh+Bl)[N,K]^T via 3 combos per K-chunk.
// A2 = [Ah|Al] (row stride 2K), B2 = [Bh|Bl]. MI=4: 128-row tile; MI=2: 64.
#define SSTRIDE 40

template<int MI, bool BIAS, bool RELU, bool RESID, bool COUT, bool SPLITOUT>
__global__ void __launch_bounds__(256, 2)
hgemm(const bf16* __restrict__ A2, const bf16* __restrict__ B2,
      float* __restrict__ C, const float* __restrict__ bias,
      const float* __restrict__ resid, bf16* __restrict__ S2,
      int M, int N, int K) {
    constexpr int AROWS = MI * 32;
    constexpr int OAh = 0;
    constexpr int OAl = AROWS * SSTRIDE;
    constexpr int OBh = 2 * AROWS * SSTRIDE;
    constexpr int OBl = 2 * AROWS * SSTRIDE + 128 * SSTRIDE;
    constexpr int SS  = 2 * AROWS * SSTRIDE + 2 * 128 * SSTRIDE;  // halves/stage
    extern __shared__ bf16 dsm[];
    int tid = threadIdx.x;
    int row0 = blockIdx.x * AROWS;
    int col0 = blockIdx.y * 128;
    int lane = tid & 31, wid = tid >> 5;
    int m0 = (wid & 1) * (MI * 16), n0 = (wid >> 1) * 32;
    int K2 = 2 * K;

    int lrow = tid >> 2;              // 0..63
    int lcol = (tid & 3) * 8;
    const bf16* pAh0 = A2 + (size_t)(row0 + lrow) * K2 + lcol;
    const bf16* pAh1 = A2 + (size_t)(row0 + lrow + 64) * K2 + lcol;   // MI=4 only
    const bf16* pBh0 = B2 + (size_t)(col0 + lrow) * K2 + lcol;
    const bf16* pBh1 = B2 + (size_t)(col0 + lrow + 64) * K2 + lcol;
    uint32_t sb = smem_u32(dsm);
    uint32_t wrow = (uint32_t)(lrow * SSTRIDE + lcol) * 2;
    uint32_t wrow64 = (uint32_t)((lrow + 64) * SSTRIDE + lcol) * 2;
    const uint32_t stageB = SS * 2;   // bytes

    float acc[MI][4][4];
    #pragma unroll
    for (int i = 0; i < MI; i++)
        #pragma unroll
        for (int j = 0; j < 4; j++)
            #pragma unroll
            for (int q = 0; q < 4; q++) acc[i][j][q] = 0.0f;

    auto load_stage = [&](int st, int k0) {
        uint32_t base = sb + (uint32_t)st * stageB;
        cp16(base + OAh*2 + wrow, pAh0 + k0);
        cp16(base + OAl*2 + wrow, pAh0 + K + k0);
        if (MI == 4) {
            cp16(base + OAh*2 + wrow64, pAh1 + k0);
            cp16(base + OAl*2 + wrow64, pAh1 + K + k0);
        }
        cp16(base + OBh*2 + wrow,   pBh0 + k0);
        cp16(base + OBl*2 + wrow,   pBh0 + K + k0);
        cp16(base + OBh*2 + wrow64, pBh1 + k0);
        cp16(base + OBl*2 + wrow64, pBh1 + K + k0);
        CP_COMMIT();
    };

    int NIT = K >> 5;
    load_stage(0, 0);

    uint32_t aoff = (uint32_t)((m0 + (lane & 15)) * SSTRIDE + (lane >> 4) * 8) * 2;
    uint32_t boff = (uint32_t)((n0 + (lane & 15)) * SSTRIDE + (lane >> 4) * 8) * 2;

    for (int it = 0; it < NIT; it++) {
        int sc = it & 1;
        if (it + 1 < NIT) { load_stage((it + 1) & 1, (it + 1) << 5); cp_wait<1>(); }
        else cp_wait<0>();
        __syncthreads();
        uint32_t base = sb + (uint32_t)sc * stageB;
        #pragma unroll
        for (int kk = 0; kk < 2; kk++) {
            uint32_t koff = (uint32_t)(kk * 16) * 2;
            uint32_t bH[2][4], bL[2][4];
            #pragma unroll
            for (int nj = 0; nj < 2; nj++) {
                uint32_t bo = boff + (uint32_t)(nj*16*SSTRIDE)*2 + koff;
                ldsm4(bH[nj][0], bH[nj][1], bH[nj][2], bH[nj][3], base + OBh*2 + bo);
                ldsm4(bL[nj][0], bL[nj][1], bL[nj][2], bL[nj][3], base + OBl*2 + bo);
            }
            #pragma unroll
            for (int mi = 0; mi < MI; mi++) {
                uint32_t ao = aoff + (uint32_t)(mi*16*SSTRIDE)*2 + koff;
                uint32_t aH[4], aL[4];
                ldsm4(aH[0], aH[1], aH[2], aH[3], base + OAh*2 + ao);
                ldsm4(aL[0], aL[1], aL[2], aL[3], base + OAl*2 + ao);
                #pragma unroll
                for (int ni = 0; ni < 4; ni++) {
                    int nj = ni >> 1, sub = ni & 1;
                    uint32_t h0 = sub ? bH[nj][1] : bH[nj][0];
                    uint32_t h1 = sub ? bH[nj][3] : bH[nj][2];
                    uint32_t l0 = sub ? bL[nj][1] : bL[nj][0];
                    uint32_t l1 = sub ? bL[nj][3] : bL[nj][2];
                    mma16816(acc[mi][ni], aH[0], aH[1], aH[2], aH[3], h0, h1);
                    mma16816(acc[mi][ni], aL[0], aL[1], aL[2], aL[3], h0, h1);
                    mma16816(acc[mi][ni], aH[0], aH[1], aH[2], aH[3], l0, l1);
                }
            }
        }
        __syncthreads();
    }

    int r4 = lane >> 2, c2 = (lane & 3) * 2;
    #pragma unroll
    for (int mi = 0; mi < MI; mi++) {
        #pragma unroll
        for (int half = 0; half < 2; half++) {
            int row = row0 + m0 + mi*16 + r4 + half*8;
            size_t rowN = (size_t)row * N;
            size_t rowS = (size_t)row * 2 * N;
            #pragma unroll
            for (int ni = 0; ni < 4; ni++) {
                int col = col0 + n0 + ni*8 + c2;
                float v0 = acc[mi][ni][half*2 + 0];
                float v1 = acc[mi][ni][half*2 + 1];
                if (BIAS) { v0 += bias[col]; v1 += bias[col + 1]; }
                if (RESID) {
                    float2 rv = *(const float2*)&resid[rowN + col];
                    v0 += rv.x; v1 += rv.y;
                }
                if (RELU) { v0 = fmaxf(v0, 0.f); v1 = fmaxf(v1, 0.f); }
                if (COUT) *(float2*)&C[rowN + col] = make_float2(v0, v1);
                if (SPLITOUT) {
                    bf16 h0, l0, h1, l1;
                    split2(v0, h0, l0); split2(v1, h1, l1);
                    __nv_bfloat162 ph; ph.x = h0; ph.y = h1;
                    __nv_bfloat162 pl; pl.x = l0; pl.y = l1;
                    *(__nv_bfloat162*)&S2[rowS + col]     = ph;
                    *(__nv_bfloat162*)&S2[rowS + N + col] = pl;
                }
            }
        }
    }
}
#define HG_SMEM(MI) ((2*((MI)*32)*SSTRIDE + 2*128*SSTRIDE) * 2 * 2)

// ---------------- flash attention (unchanged math; qkv2 stride) ------------
#define FPAD 72
#define FQL 9216
#define FKV 18432
#define FSTG 36864
#define FLASH_SMEM ((FKV + 2*FSTG) * 2)

__global__ void __launch_bounds__(256, 1)
flash_kernel(const bf16* __restrict__ qkv2, bf16* __restrict__ as2) {
    extern __shared__ bf16 fsm[];
    uint32_t sbase = smem_u32(fsm);
    int tid = threadIdx.x, lane = tid & 31, wid = tid >> 5;
    int z = blockIdx.x;
    int qt = 15 - (z >> 4);
    int bh = z & 15;
    int b = bh >> 3, h = bh & 7;
    int grow0 = b * Td + qt * 128;
    int m0 = wid * 16;

    int r2 = tid >> 1, c32 = (tid & 1) * 32;
    {
        const bf16* src = qkv2 + (size_t)(grow0 + r2) * QKV2W + c32;
        uint32_t d = sbase + (uint32_t)(r2 * FPAD + c32) * 2;
        #pragma unroll
        for (int j = 0; j < 4; j++) {
            cp16(d + j*16,          src + h*64 + j*8);
            cp16(d + FQL*2 + j*16,  src + 1536 + h*64 + j*8);
        }
    }
    auto load_kv = [&](int stage, int kv) {
        const bf16* src = qkv2 + (size_t)(b * Td + kv * 128 + r2) * QKV2W + c32;
        uint32_t d = sbase + (uint32_t)(FKV + stage*FSTG + r2 * FPAD + c32) * 2;
        #pragma unroll
        for (int j = 0; j < 4; j++) {
            cp16(d + j*16,            src + 512 + h*64 + j*8);
            cp16(d + FQL*2 + j*16,    src + 1536 + 512 + h*64 + j*8);
            cp16(d + FQL*4 + j*16,    src + 1024 + h*64 + j*8);
            cp16(d + FQL*6 + j*16,    src + 1536 + 1024 + h*64 + j*8);
        }
    };
    load_kv(0, 0);
    CP_COMMIT();

    float m[2] = {-1e30f, -1e30f}, l[2] = {0.f, 0.f};
    float O[8][4];
    #pragma unroll
    for (int f = 0; f < 8; f++)
        #pragma unroll
        for (int e = 0; e < 4; e++) O[f][e] = 0.f;

    int nkv = qt + 1;
    int r4 = lane >> 2, c2 = (lane & 3) * 2;
    int rowg0 = qt*128 + m0 + r4;

    for (int kv = 0; kv < nkv; kv++) {
        if (kv + 1 < nkv) { load_kv((kv + 1) & 1, kv + 1); CP_COMMIT(); cp_wait<1>(); }
        else cp_wait<0>();
        __syncthreads();
        uint32_t kb = sbase + (uint32_t)(FKV + (kv & 1) * FSTG) * 2;

        float S[16][4];
        #pragma unroll
        for (int f = 0; f < 16; f++)
            #pragma unroll
            for (int e = 0; e < 4; e++) S[f][e] = 0.f;
        #pragma unroll
        for (int kc = 0; kc < 4; kc++) {
            uint32_t qa = sbase + (uint32_t)((m0 + (lane & 15)) * FPAD + kc*16 + (lane >> 4)*8) * 2;
            uint32_t aH[4], aL[4];
            ldsm4(aH[0], aH[1], aH[2], aH[3], qa);
            ldsm4(aL[0], aL[1], aL[2], aL[3], qa + FQL*2);
            #pragma unroll
            for (int ng = 0; ng < 8; ng++) {
                uint32_t ka = kb + (uint32_t)((ng*16 + (lane & 15)) * FPAD + kc*16 + (lane >> 4)*8) * 2;
                uint32_t bH[4], bL[4];
                ldsm4(bH[0], bH[1], bH[2], bH[3], ka);
                ldsm4(bL[0], bL[1], bL[2], bL[3], ka + FQL*2);
                #pragma unroll
                for (int sub = 0; sub < 2; sub++) {
                    float* c = S[ng*2 + sub];
                    uint32_t b0 = sub ? bH[1] : bH[0], b1 = sub ? bH[3] : bH[2];
                    uint32_t l0 = sub ? bL[1] : bL[0], l1 = sub ? bL[3] : bL[2];
                    mma16816(c, aH[0], aH[1], aH[2], aH[3], b0, b1);
                    mma16816(c, aL[0], aL[1], aL[2], aL[3], b0, b1);
                    mma16816(c, aH[0], aH[1], aH[2], aH[3], l0, l1);
                }
            }
        }

        if (kv == qt) {
            #pragma unroll
            for (int f = 0; f < 16; f++) {
                int colb = kv*128 + f*8 + c2;
                #pragma unroll
                for (int e = 0; e < 4; e++) {
                    int col = colb + (e & 1);
                    int row = rowg0 + ((e & 2) ? 8 : 0);
                    if (col > row) S[f][e] = -1e30f;
                }
            }
        }

        float mx0 = -1e30f, mx1 = -1e30f;
        #pragma unroll
        for (int f = 0; f < 16; f++) {
            mx0 = fmaxf(mx0, fmaxf(S[f][0], S[f][1]));
            mx1 = fmaxf(mx1, fmaxf(S[f][2], S[f][3]));
        }
        mx0 = fmaxf(mx0, __shfl_xor_sync(0xffffffff, mx0, 1));
        mx0 = fmaxf(mx0, __shfl_xor_sync(0xffffffff, mx0, 2));
        mx1 = fmaxf(mx1, __shfl_xor_sync(0xffffffff, mx1, 1));
        mx1 = fmaxf(mx1, __shfl_xor_sync(0xffffffff, mx1, 2));
        float mn0 = fmaxf(m[0], mx0), mn1 = fmaxf(m[1], mx1);
        float a0 = __expf(m[0] - mn0), a1 = __expf(m[1] - mn1);
        m[0] = mn0; m[1] = mn1;
        float s0 = 0.f, s1 = 0.f;
        #pragma unroll
        for (int f = 0; f < 16; f++) {
            S[f][0] = __expf(S[f][0] - mn0);
            S[f][1] = __expf(S[f][1] - mn0);
            S[f][2] = __expf(S[f][2] - mn1);
            S[f][3] = __expf(S[f][3] - mn1);
            s0 += S[f][0] + S[f][1];
            s1 += S[f][2] + S[f][3];
        }
        s0 += __shfl_xor_sync(0xffffffff, s0, 1);
        s0 += __shfl_xor_sync(0xffffffff, s0, 2);
        s1 += __shfl_xor_sync(0xffffffff, s1, 1);
        s1 += __shfl_xor_sync(0xffffffff, s1, 2);
        l[0] = l[0] * a0 + s0;
        l[1] = l[1] * a1 + s1;
        #pragma unroll
        for (int f = 0; f < 8; f++) {
            O[f][0] *= a0; O[f][1] *= a0;
            O[f][2] *= a1; O[f][3] *= a1;
        }

        int kr = (lane & 7) + ((lane & 16) ? 8 : 0);
        int nc8 = (lane & 8) ? 8 : 0;
        #pragma unroll
        for (int kc = 0; kc < 8; kc++) {
            uint32_t pha[4], pla[4];
            #pragma unroll
            for (int q = 0; q < 2; q++) {
                int f = kc*2 + q;
                #pragma unroll
                for (int rh = 0; rh < 2; rh++) {
                    float x = S[f][rh*2], y = S[f][rh*2 + 1];
                    bf16 hx = __float2bfloat16_rn(x);
                    bf16 hy = __float2bfloat16_rn(y);
                    float lx = x - __bfloat162float(hx);
                    float ly = y - __bfloat162float(hy);
                    __nv_bfloat162 ph; ph.x = hx; ph.y = hy;
                    pha[q*2 + rh] = *(uint32_t*)&ph;
                    pla[q*2 + rh] = packbf(lx, ly);
                }
            }
            #pragma unroll
            for (int ng2 = 0; ng2 < 4; ng2++) {
                uint32_t va = kb + (uint32_t)((2*FQL) + (kc*16 + kr) * FPAD + ng2*16 + nc8) * 2;
                uint32_t vH[4], vL[4];
                ldsm4t(vH[0], vH[1], vH[2], vH[3], va);
                ldsm4t(vL[0], vL[1], vL[2], vL[3], va + FQL*2);
                #pragma unroll
                for (int sub = 0; sub < 2; sub++) {
                    float* c = O[ng2*2 + sub];
                    uint32_t b0 = sub ? vH[1] : vH[0], b1 = sub ? vH[3] : vH[2];
                    uint32_t l0 = sub ? vL[1] : vL[0], l1 = sub ? vL[3] : vL[2];
                    mma16816(c, pha[0], pha[1], pha[2], pha[3], b0, b1);
                    mma16816(c, pla[0], pla[1], pla[2], pla[3], b0, b1);
                    mma16816(c, pha[0], pha[1], pha[2], pha[3], l0, l1);
                }
            }
        }
        __syncthreads();
    }

    float i0 = 1.f / l[0], i1 = 1.f / l[1];
    int rg0 = grow0 + m0 + r4;
    #pragma unroll
    for (int f = 0; f < 8; f++) {
        int col = h*64 + f*8 + c2;
        float v0 = O[f][0] * i0, v1 = O[f][1] * i0;
        float w0 = O[f][2] * i1, w1 = O[f][3] * i1;
        size_t rS0 = (size_t)rg0 * 1024;
        size_t rS1 = (size_t)(rg0 + 8) * 1024;
        bf16 h0, l0h, h1, l1h;
        split2(v0, h0, l0h); split2(v1, h1, l1h);
        __nv_bfloat162 ph; ph.x = h0; ph.y = h1;
        __nv_bfloat162 pl; pl.x = l0h; pl.y = l1h;
        *(__nv_bfloat162*)&as2[rS0 + col]       = ph;
        *(__nv_bfloat162*)&as2[rS0 + 512 + col] = pl;
        split2(w0, h0, l0h); split2(w1, h1, l1h);
        ph.x = h0; ph.y = h1; pl.x = l0h; pl.y = l1h;
        *(__nv_bfloat162*)&as2[rS1 + col]       = ph;
        *(__nv_bfloat162*)&as2[rS1 + 512 + col] = pl;
    }
}

// ---------------- small kernels --------------------------------------------
__global__ void embed_kernel(const int* __restrict__ idx, const float* __restrict__ tok,
                             const float* __restrict__ pos, float* __restrict__ out) {
    int r = blockIdx.x;
    int t = r & (Td - 1);
    int token = idx[r];
    int c = threadIdx.x;
    const float* tp = tok + (size_t)token * Cd;
    const float* pp = pos + (size_t)t * Cd;
    float* op = out + (size_t)r * Cd;
    op[c] = tp[c] + pp[c];
    op[c + 256] = tp[c + 256] + pp[c + 256];
}

template<bool ADD, bool FOUT>
__global__ void ln_kernel(const float* __restrict__ in, float* __restrict__ out,
                          const float* __restrict__ gw, const float* __restrict__ bw,
                          const float* __restrict__ add, bf16* __restrict__ s2) {
    int r = blockIdx.x;
    const float* x = in + (size_t)r * Cd;
    int tid = threadIdx.x;
    float v0 = x[tid], v1 = x[tid + 256];
    __shared__ float rs[256], rq[256];
    rs[tid] = v0 + v1;
    rq[tid] = v0 * v0 + v1 * v1;
    __syncthreads();
    #pragma unroll
    for (int off = 128; off > 0; off >>= 1) {
        if (tid < off) { rs[tid] += rs[tid+off]; rq[tid] += rq[tid+off]; }
        __syncthreads();
    }
    float mean = rs[0] * (1.0f / Cd);
    float var = rq[0] * (1.0f / Cd) - mean * mean;
    float inv = rsqrtf(var + 1e-5f);
    float o0 = (v0 - mean) * inv * gw[tid] + bw[tid];
    float o1 = (v1 - mean) * inv * gw[tid+256] + bw[tid+256];
    if (ADD) {
        o0 += add[(size_t)r * Cd + tid];
        o1 += add[(size_t)r * Cd + tid + 256];
    }
    if (FOUT) {
        out[(size_t)r * Cd + tid] = o0;
        out[(size_t)r * Cd + tid + 256] = o1;
    }
    bf16 h, l;
    size_t base = (size_t)r * 2 * Cd;
    split2(o0, h, l);
    s2[base + tid] = h; s2[base + Cd + tid] = l;
    split2(o1, h, l);
    s2[base + tid + 256] = h; s2[base + Cd + tid + 256] = l;
}

__global__ void prep_qkv_w(const float* __restrict__ wq, const float* __restrict__ wk,
                           const float* __restrict__ wv, bf16* __restrict__ o2) {
    int i = blockIdx.x * 256 + threadIdx.x;
    if (i >= Ld * QKVW * Cd) return;
    int k = i % Cd;
    int n = (i / Cd) % QKVW;
    int l = i / (Cd * QKVW);
    int which = n >> 9, h = (n >> 6) & 7, d = n & 63;
    const float* src = (which == 0) ? wq : (which == 1) ? wk : wv;
    float v = src[(((size_t)l * Hd + h) * Cd + k) * HSd + d];
    bf16 hh, ll; split2(v, hh, ll);
    size_t base = ((size_t)l * QKVW + n) * 2 * Cd;
    o2[base + k] = hh; o2[base + Cd + k] = ll;
}
__global__ void split_b2(const float* __restrict__ in, bf16* __restrict__ o2,
                         int n, int W) {
    int i = blockIdx.x * 256 + threadIdx.x;
    if (i >= n) return;
    int r = i / W, k = i - r * W;
    bf16 h, l; split2(in[i], h, l);
    size_t base = (size_t)r * 2 * W;
    o2[base + k] = h; o2[base + W + k] = l;
}
__global__ void transpose_b2(const float* __restrict__ in, bf16* __restrict__ o2,
                             int K, int N) {
    __shared__ float tsm[32][33];
    in += (size_t)blockIdx.z * K * N;
    o2 += (size_t)blockIdx.z * N * 2 * K;
    int n0 = blockIdx.x * 32, k0 = blockIdx.y * 32;
    for (int j = threadIdx.y; j < 32; j += 8)
        tsm[j][threadIdx.x] = in[(size_t)(k0 + j) * N + n0 + threadIdx.x];
    __syncthreads();
    for (int i = threadIdx.y; i < 32; i += 8) {
        float v = tsm[threadIdx.x][i];
        bf16 h, l; split2(v, h, l);
        size_t base = (size_t)(n0 + i) * 2 * K;
        int k = k0 + threadIdx.x;
        o2[base + k] = h; o2[base + K + k] = l;
    }
}

// ---------------- host -----------------------------------------------------
extern "C" void kernel_launch(void* const* d_in, const int* in_sizes, int n_in,
                              void* d_out, int out_size) {
    const int*   idx     = (const int*)  d_in[0];
    const float* tok_emb = (const float*)d_in[1];
    const float* pos_emb = (const float*)d_in[2];
    const float* ln1_g   = (const float*)d_in[3];
    const float* ln1_b   = (const float*)d_in[4];
    const float* wq      = (const float*)d_in[5];
    const float* wk      = (const float*)d_in[6];
    const float* wv      = (const float*)d_in[7];
    const float* proj_w  = (const float*)d_in[8];
    const float* proj_b  = (const float*)d_in[9];
    const float* ln2_g   = (const float*)d_in[10];
    const float* ln2_b   = (const float*)d_in[11];
    const float* ff_w1   = (const float*)d_in[12];
    const float* ff_b1   = (const float*)d_in[13];
    const float* ff_w2   = (const float*)d_in[14];
    const float* ff_b2   = (const float*)d_in[15];
    const float* ffln_g  = (const float*)d_in[16];
    const float* ffln_b  = (const float*)d_in[17];
    const float* lm_w    = (const float*)d_in[18];
    const float* lm_b    = (const float*)d_in[19];
    float* out = (float*)d_out;

    float *x, *ff2;
    cudaGetSymbolAddress((void**)&x,   g_x);
    cudaGetSymbolAddress((void**)&ff2, g_ff2);
    bf16 *qkv2, *hs2, *as2, *xs2, *f12, *wqkv2, *wproj2, *wff12, *wff22, *wlm2;
    cudaGetSymbolAddress((void**)&qkv2,  g_qkv2);
    cudaGetSymbolAddress((void**)&hs2,   g_hs2);
    cudaGetSymbolAddress((void**)&as2,   g_as2);
    cudaGetSymbolAddress((void**)&xs2,   g_xs2);
    cudaGetSymbolAddress((void**)&f12,   g_f12);
    cudaGetSymbolAddress((void**)&wqkv2, g_wqkv2);
    cudaGetSymbolAddress((void**)&wproj2,g_wproj2);
    cudaGetSymbolAddress((void**)&wff12, g_wff12);
    cudaGetSymbolAddress((void**)&wff22, g_wff22);
    cudaGetSymbolAddress((void**)&wlm2,  g_wlm2);

    cudaFuncSetAttribute(flash_kernel, cudaFuncAttributeMaxDynamicSharedMemorySize, FLASH_SMEM);
    cudaFuncSetAttribute(hgemm<4,false,false,false,false,true>, cudaFuncAttributeMaxDynamicSharedMemorySize, HG_SMEM(4));
    cudaFuncSetAttribute(hgemm<2,true,false,true,true,false>,  cudaFuncAttributeMaxDynamicSharedMemorySize, HG_SMEM(2));
    cudaFuncSetAttribute(hgemm<4,true,true,false,false,true>,  cudaFuncAttributeMaxDynamicSharedMemorySize, HG_SMEM(4));
    cudaFuncSetAttribute(hgemm<2,true,false,false,true,false>, cudaFuncAttributeMaxDynamicSharedMemorySize, HG_SMEM(2));
    cudaFuncSetAttribute(hgemm<4,true,false,false,true,false>, cudaFuncAttributeMaxDynamicSharedMemorySize, HG_SMEM(4));

    embed_kernel<<<NT, 256>>>(idx, tok_emb, pos_emb, x);
    prep_qkv_w<<<(Ld*QKVW*Cd + 255)/256, 256>>>(wq, wk, wv, wqkv2);
    split_b2<<<(Ld*Cd*Cd + 255)/256, 256>>>(proj_w, wproj2, Ld*Cd*Cd, Cd);
    transpose_b2<<<dim3(FFW/32, Cd/32, Ld), dim3(32,8)>>>(ff_w1, wff12, Cd, FFW);
    transpose_b2<<<dim3(Cd/32, FFW/32, Ld), dim3(32,8)>>>(ff_w2, wff22, FFW, Cd);
    transpose_b2<<<dim3(Vd/32, Cd/32, 1),  dim3(32,8)>>>(lm_w, wlm2, Cd, Vd);

    for (int l = 0; l < Ld; l++) {
        ln_kernel<false,false><<<NT, 256>>>(x, nullptr, ln1_g + l*Cd, ln1_b + l*Cd,
                                            nullptr, hs2);
        hgemm<4,false,false,false,false,true><<<dim3(NT/128, QKVW/128), 256, HG_SMEM(4)>>>(
            hs2, wqkv2 + (size_t)l*QKVW*2*Cd, nullptr, nullptr, nullptr, qkv2,
            NT, QKVW, Cd);
        flash_kernel<<<256, 256, FLASH_SMEM>>>(qkv2, as2);
        hgemm<2,true,false,true,true,false><<<dim3(NT/64, Cd/128), 256, HG_SMEM(2)>>>(
            as2, wproj2 + (size_t)l*Cd*2*Cd, x, proj_b + l*Cd, x, nullptr,
            NT, Cd, Cd);
        ln_kernel<false,false><<<NT, 256>>>(x, nullptr, ln2_g + l*Cd, ln2_b + l*Cd,
                                            nullptr, hs2);
        hgemm<4,true,true,false,false,true><<<dim3(NT/128, FFW/128), 256, HG_SMEM(4)>>>(
            hs2, wff12 + (size_t)l*FFW*2*Cd, nullptr, ff_b1 + l*FFW, nullptr, f12,
            NT, FFW, Cd);
        hgemm<2,true,false,false,true,false><<<dim3(NT/64, Cd/128), 256, HG_SMEM(2)>>>(
            f12, wff22 + (size_t)l*Cd*2*FFW, ff2, ff_b2 + l*Cd, nullptr, nullptr,
            NT, Cd, FFW);
        ln_kernel<true,true><<<NT, 256>>>(ff2, x, ffln_g + l*Cd, ffln_b + l*Cd,
                                          x, xs2);
    }
    hgemm<4,true,false,false,true,false><<<dim3(NT/128, Vd/128), 256, HG_SMEM(4)>>>(
        xs2, wlm2, out, lm_b, nullptr, nullptr, NT, Vd, Cd);
}

// round 11
// speedup vs baseline: 3.0967x; 1.0226x over previous
#include <cuda_runtime.h>
#include <cuda_bf16.h>
#include <cstdint>

#define Bd 2
#define Td 2048
#define Cd 512
#define Hd 8
#define HSd 64
#define Ld 4
#define Vd 32000
#define NT (Bd*Td)
#define QKVW (3*Cd)
#define FFW (4*Cd)
#define QKV2W (2*QKVW)       // 3072

typedef __nv_bfloat16 bf16;

// ---------------- scratch --------------------------------------------------
__device__ float g_x   [NT*Cd];
__device__ float g_ff2 [NT*Cd];
__device__ bf16 g_qkv2[(size_t)NT*QKV2W];      // [Qh Kh Vh | Ql Kl Vl]
__device__ bf16 g_hs2 [NT*2*Cd];
__device__ bf16 g_as2 [NT*2*Cd];
__device__ bf16 g_xs2 [NT*2*Cd];
__device__ bf16 g_f12 [NT*2*FFW];
__device__ bf16 g_wqkv2 [Ld*QKVW*2*Cd];
__device__ bf16 g_wproj2[Ld*Cd*2*Cd];
__device__ bf16 g_wff12 [Ld*FFW*2*Cd];
__device__ bf16 g_wff22 [Ld*Cd*2*FFW];
__device__ bf16 g_wlm2  [(size_t)Vd*2*Cd];

// ---------------- helpers --------------------------------------------------
__device__ __forceinline__ uint32_t smem_u32(const void* p) {
    uint32_t a;
    asm("{ .reg .u64 t; cvta.to.shared.u64 t, %1; cvt.u32.u64 %0, t; }" : "=r"(a) : "l"(p));
    return a;
}
__device__ __forceinline__ void cp16(uint32_t d, const void* s) {
    asm volatile("cp.async.cg.shared.global [%0], [%1], 16;" :: "r"(d), "l"(s));
}
#define CP_COMMIT() asm volatile("cp.async.commit_group;" ::: "memory")
template<int N> __device__ __forceinline__ void cp_wait() {
    asm volatile("cp.async.wait_group %0;" :: "n"(N) : "memory");
}
__device__ __forceinline__ void ldsm4(uint32_t& r0, uint32_t& r1, uint32_t& r2,
                                      uint32_t& r3, uint32_t addr) {
    asm volatile("ldmatrix.sync.aligned.m8n8.x4.shared.b16 {%0,%1,%2,%3}, [%4];"
                 : "=r"(r0), "=r"(r1), "=r"(r2), "=r"(r3) : "r"(addr));
}
__device__ __forceinline__ void ldsm4t(uint32_t& r0, uint32_t& r1, uint32_t& r2,
                                       uint32_t& r3, uint32_t addr) {
    asm volatile("ldmatrix.sync.aligned.m8n8.x4.trans.shared.b16 {%0,%1,%2,%3}, [%4];"
                 : "=r"(r0), "=r"(r1), "=r"(r2), "=r"(r3) : "r"(addr));
}
__device__ __forceinline__ void mma16816(float* c, uint32_t a0, uint32_t a1,
                                         uint32_t a2, uint32_t a3,
                                         uint32_t b0, uint32_t b1) {
    asm volatile(
        "mma.sync.aligned.m16n8k16.row.col.f32.bf16.bf16.f32 "
        "{%0,%1,%2,%3}, {%4,%5,%6,%7}, {%8,%9}, {%0,%1,%2,%3};"
        : "+f"(c[0]), "+f"(c[1]), "+f"(c[2]), "+f"(c[3])
        : "r"(a0), "r"(a1), "r"(a2), "r"(a3), "r"(b0), "r"(b1));
}
__device__ __forceinline__ void split2(float v, bf16& h, bf16& l) {
    h = __float2bfloat16_rn(v);
    l = __float2bfloat16_rn(v - __bfloat162float(h));
}
__device__ __forceinline__ uint32_t packbf(float x, float y) {
    __nv_bfloat162 t = __floats2bfloat162_rn(x, y);
    return *(uint32_t*)&t;
}

// ---------------- combo HMMA GEMM ------------------------------------------
// C[M,N] = (Ah+Al)[M,K].(Bh+Bl)[N,K]^T via 3 combos per K-chunk.
// A2 = [Ah|Al] (row stride 2K), B2 = [Bh|Bl].
// STAGES-deep cp.async pipeline; ONE __syncthreads per iter.
#define SSTRIDE 40
#define HG_SMEM(MI,S) ((2*((MI)*32)*SSTRIDE + 2*128*SSTRIDE) * 2 * (S))

template<int MI, int STAGES, bool BIAS, bool RELU, bool RESID, bool COUT, bool SPLITOUT>
__global__ void __launch_bounds__(256, 2)
hgemm(const bf16* __restrict__ A2, const bf16* __restrict__ B2,
      float* __restrict__ C, const float* __restrict__ bias,
      const float* __restrict__ resid, bf16* __restrict__ S2,
      int M, int N, int K) {
    constexpr int AROWS = MI * 32;
    constexpr int OAh = 0;
    constexpr int OAl = AROWS * SSTRIDE;
    constexpr int OBh = 2 * AROWS * SSTRIDE;
    constexpr int OBl = 2 * AROWS * SSTRIDE + 128 * SSTRIDE;
    constexpr int SS  = 2 * AROWS * SSTRIDE + 2 * 128 * SSTRIDE;  // halves/stage
    extern __shared__ bf16 dsm[];
    int tid = threadIdx.x;
    int row0 = blockIdx.x * AROWS;
    int col0 = blockIdx.y * 128;
    int lane = tid & 31, wid = tid >> 5;
    int m0 = (wid & 1) * (MI * 16), n0 = (wid >> 1) * 32;
    int K2 = 2 * K;

    int lrow = tid >> 2;              // 0..63
    int lcol = (tid & 3) * 8;
    const bf16* pAh0 = A2 + (size_t)(row0 + lrow) * K2 + lcol;
    const bf16* pAh1 = A2 + (size_t)(row0 + lrow + 64) * K2 + lcol;   // MI=4 only
    const bf16* pBh0 = B2 + (size_t)(col0 + lrow) * K2 + lcol;
    const bf16* pBh1 = B2 + (size_t)(col0 + lrow + 64) * K2 + lcol;
    uint32_t sb = smem_u32(dsm);
    uint32_t wrow = (uint32_t)(lrow * SSTRIDE + lcol) * 2;
    uint32_t wrow64 = (uint32_t)((lrow + 64) * SSTRIDE + lcol) * 2;
    const uint32_t stageB = SS * 2;   // bytes

    float acc[MI][4][4];
    #pragma unroll
    for (int i = 0; i < MI; i++)
        #pragma unroll
        for (int j = 0; j < 4; j++)
            #pragma unroll
            for (int q = 0; q < 4; q++) acc[i][j][q] = 0.0f;

    auto load_stage = [&](int st, int k0) {
        uint32_t base = sb + (uint32_t)st * stageB;
        cp16(base + OAh*2 + wrow, pAh0 + k0);
        cp16(base + OAl*2 + wrow, pAh0 + K + k0);
        if (MI == 4) {
            cp16(base + OAh*2 + wrow64, pAh1 + k0);
            cp16(base + OAl*2 + wrow64, pAh1 + K + k0);
        }
        cp16(base + OBh*2 + wrow,   pBh0 + k0);
        cp16(base + OBl*2 + wrow,   pBh0 + K + k0);
        cp16(base + OBh*2 + wrow64, pBh1 + k0);
        cp16(base + OBl*2 + wrow64, pBh1 + K + k0);
        CP_COMMIT();
    };

    int NIT = K >> 5;
    #pragma unroll
    for (int s = 0; s < STAGES - 1; s++) load_stage(s, s << 5);

    uint32_t aoff = (uint32_t)((m0 + (lane & 15)) * SSTRIDE + (lane >> 4) * 8) * 2;
    uint32_t boff = (uint32_t)((n0 + (lane & 15)) * SSTRIDE + (lane >> 4) * 8) * 2;

    int cur = 0, nxt = STAGES - 1;
    for (int it = 0; it < NIT; it++) {
        cp_wait<STAGES - 2>();
        __syncthreads();
        int nk = it + STAGES - 1;
        if (nk < NIT) load_stage(nxt, nk << 5);
        nxt = (nxt + 1 == STAGES) ? 0 : nxt + 1;
        uint32_t base = sb + (uint32_t)cur * stageB;
        cur = (cur + 1 == STAGES) ? 0 : cur + 1;
        #pragma unroll
        for (int kk = 0; kk < 2; kk++) {
            uint32_t koff = (uint32_t)(kk * 16) * 2;
            uint32_t bH[2][4], bL[2][4];
            #pragma unroll
            for (int nj = 0; nj < 2; nj++) {
                uint32_t bo = boff + (uint32_t)(nj*16*SSTRIDE)*2 + koff;
                ldsm4(bH[nj][0], bH[nj][1], bH[nj][2], bH[nj][3], base + OBh*2 + bo);
                ldsm4(bL[nj][0], bL[nj][1], bL[nj][2], bL[nj][3], base + OBl*2 + bo);
            }
            #pragma unroll
            for (int mi = 0; mi < MI; mi++) {
                uint32_t ao = aoff + (uint32_t)(mi*16*SSTRIDE)*2 + koff;
                uint32_t aH[4], aL[4];
                ldsm4(aH[0], aH[1], aH[2], aH[3], base + OAh*2 + ao);
                ldsm4(aL[0], aL[1], aL[2], aL[3], base + OAl*2 + ao);
                #pragma unroll
                for (int ni = 0; ni < 4; ni++) {
                    int nj = ni >> 1, sub = ni & 1;
                    uint32_t h0 = sub ? bH[nj][1] : bH[nj][0];
                    uint32_t h1 = sub ? bH[nj][3] : bH[nj][2];
                    uint32_t l0 = sub ? bL[nj][1] : bL[nj][0];
                    uint32_t l1 = sub ? bL[nj][3] : bL[nj][2];
                    mma16816(acc[mi][ni], aH[0], aH[1], aH[2], aH[3], h0, h1);
                    mma16816(acc[mi][ni], aL[0], aL[1], aL[2], aL[3], h0, h1);
                    mma16816(acc[mi][ni], aH[0], aH[1], aH[2], aH[3], l0, l1);
                }
            }
        }
    }

    int r4 = lane >> 2, c2 = (lane & 3) * 2;
    #pragma unroll
    for (int mi = 0; mi < MI; mi++) {
        #pragma unroll
        for (int half = 0; half < 2; half++) {
            int row = row0 + m0 + mi*16 + r4 + half*8;
            size_t rowN = (size_t)row * N;
            size_t rowS = (size_t)row * 2 * N;
            #pragma unroll
            for (int ni = 0; ni < 4; ni++) {
                int col = col0 + n0 + ni*8 + c2;
                float v0 = acc[mi][ni][half*2 + 0];
                float v1 = acc[mi][ni][half*2 + 1];
                if (BIAS) { v0 += bias[col]; v1 += bias[col + 1]; }
                if (RESID) {
                    float2 rv = *(const float2*)&resid[rowN + col];
                    v0 += rv.x; v1 += rv.y;
                }
                if (RELU) { v0 = fmaxf(v0, 0.f); v1 = fmaxf(v1, 0.f); }
                if (COUT) *(float2*)&C[rowN + col] = make_float2(v0, v1);
                if (SPLITOUT) {
                    bf16 h0, l0, h1, l1;
                    split2(v0, h0, l0); split2(v1, h1, l1);
                    __nv_bfloat162 ph; ph.x = h0; ph.y = h1;
                    __nv_bfloat162 pl; pl.x = l0; pl.y = l1;
                    *(__nv_bfloat162*)&S2[rowS + col]     = ph;
                    *(__nv_bfloat162*)&S2[rowS + N + col] = pl;
                }
            }
        }
    }
}

// ---------------- flash attention (persistent, heavy-first pairing) --------
#define FPAD 72
#define FQL 9216
#define FKV 18432
#define FSTG 36864
#define FLASH_SMEM ((FKV + 2*FSTG) * 2)

__global__ void __launch_bounds__(256, 1)
flash_kernel(const bf16* __restrict__ qkv2, bf16* __restrict__ as2) {
    extern __shared__ bf16 fsm[];
    uint32_t sbase = smem_u32(fsm);
    int tid = threadIdx.x, lane = tid & 31, wid = tid >> 5;
    int bid = blockIdx.x;                 // 0..147
    int nitems = (bid >= 40) ? 2 : 1;     // item bid, plus item 295-bid
    int r2 = tid >> 1, c32 = (tid & 1) * 32;
    int m0 = wid * 16;
    int r4 = lane >> 2, c2 = (lane & 3) * 2;

    for (int ii = 0; ii < nitems; ii++) {
        int z = (ii == 0) ? bid : (295 - bid);
        int qt = 15 - (z >> 4);
        int bh = z & 15;
        int b = bh >> 3, h = bh & 7;
        int grow0 = b * Td + qt * 128;

        {   // Q (hi at col h*64, lo at 1536+h*64)
            const bf16* src = qkv2 + (size_t)(grow0 + r2) * QKV2W + c32;
            uint32_t d = sbase + (uint32_t)(r2 * FPAD + c32) * 2;
            #pragma unroll
            for (int j = 0; j < 4; j++) {
                cp16(d + j*16,          src + h*64 + j*8);
                cp16(d + FQL*2 + j*16,  src + 1536 + h*64 + j*8);
            }
        }
        auto load_kv = [&](int stage, int kv) {
            const bf16* src = qkv2 + (size_t)(b * Td + kv * 128 + r2) * QKV2W + c32;
            uint32_t d = sbase + (uint32_t)(FKV + stage*FSTG + r2 * FPAD + c32) * 2;
            #pragma unroll
            for (int j = 0; j < 4; j++) {
                cp16(d + j*16,            src + 512 + h*64 + j*8);
                cp16(d + FQL*2 + j*16,    src + 1536 + 512 + h*64 + j*8);
                cp16(d + FQL*4 + j*16,    src + 1024 + h*64 + j*8);
                cp16(d + FQL*6 + j*16,    src + 1536 + 1024 + h*64 + j*8);
            }
        };
        load_kv(0, 0);
        CP_COMMIT();

        float m[2] = {-1e30f, -1e30f}, l[2] = {0.f, 0.f};
        float O[8][4];
        #pragma unroll
        for (int f = 0; f < 8; f++)
            #pragma unroll
            for (int e = 0; e < 4; e++) O[f][e] = 0.f;

        int nkv = qt + 1;
        int rowg0 = qt*128 + m0 + r4;

        for (int kv = 0; kv < nkv; kv++) {
            if (kv + 1 < nkv) { load_kv((kv + 1) & 1, kv + 1); CP_COMMIT(); cp_wait<1>(); }
            else cp_wait<0>();
            __syncthreads();
            uint32_t kb = sbase + (uint32_t)(FKV + (kv & 1) * FSTG) * 2;

            float S[16][4];
            #pragma unroll
            for (int f = 0; f < 16; f++)
                #pragma unroll
                for (int e = 0; e < 4; e++) S[f][e] = 0.f;
            #pragma unroll
            for (int kc = 0; kc < 4; kc++) {
                uint32_t qa = sbase + (uint32_t)((m0 + (lane & 15)) * FPAD + kc*16 + (lane >> 4)*8) * 2;
                uint32_t aH[4], aL[4];
                ldsm4(aH[0], aH[1], aH[2], aH[3], qa);
                ldsm4(aL[0], aL[1], aL[2], aL[3], qa + FQL*2);
                #pragma unroll
                for (int ng = 0; ng < 8; ng++) {
                    uint32_t ka = kb + (uint32_t)((ng*16 + (lane & 15)) * FPAD + kc*16 + (lane >> 4)*8) * 2;
                    uint32_t bH[4], bL[4];
                    ldsm4(bH[0], bH[1], bH[2], bH[3], ka);
                    ldsm4(bL[0], bL[1], bL[2], bL[3], ka + FQL*2);
                    #pragma unroll
                    for (int sub = 0; sub < 2; sub++) {
                        float* c = S[ng*2 + sub];
                        uint32_t b0 = sub ? bH[1] : bH[0], b1 = sub ? bH[3] : bH[2];
                        uint32_t l0 = sub ? bL[1] : bL[0], l1 = sub ? bL[3] : bL[2];
                        mma16816(c, aH[0], aH[1], aH[2], aH[3], b0, b1);
                        mma16816(c, aL[0], aL[1], aL[2], aL[3], b0, b1);
                        mma16816(c, aH[0], aH[1], aH[2], aH[3], l0, l1);
                    }
                }
            }

            if (kv == qt) {
                #pragma unroll
                for (int f = 0; f < 16; f++) {
                    int colb = kv*128 + f*8 + c2;
                    #pragma unroll
                    for (int e = 0; e < 4; e++) {
                        int col = colb + (e & 1);
                        int row = rowg0 + ((e & 2) ? 8 : 0);
                        if (col > row) S[f][e] = -1e30f;
                    }
                }
            }

            float mx0 = -1e30f, mx1 = -1e30f;
            #pragma unroll
            for (int f = 0; f < 16; f++) {
                mx0 = fmaxf(mx0, fmaxf(S[f][0], S[f][1]));
                mx1 = fmaxf(mx1, fmaxf(S[f][2], S[f][3]));
            }
            mx0 = fmaxf(mx0, __shfl_xor_sync(0xffffffff, mx0, 1));
            mx0 = fmaxf(mx0, __shfl_xor_sync(0xffffffff, mx0, 2));
            mx1 = fmaxf(mx1, __shfl_xor_sync(0xffffffff, mx1, 1));
            mx1 = fmaxf(mx1, __shfl_xor_sync(0xffffffff, mx1, 2));
            float mn0 = fmaxf(m[0], mx0), mn1 = fmaxf(m[1], mx1);
            float a0 = __expf(m[0] - mn0), a1 = __expf(m[1] - mn1);
            m[0] = mn0; m[1] = mn1;
            float s0 = 0.f, s1 = 0.f;
            #pragma unroll
            for (int f = 0; f < 16; f++) {
                S[f][0] = __expf(S[f][0] - mn0);
                S[f][1] = __expf(S[f][1] - mn0);
                S[f][2] = __expf(S[f][2] - mn1);
                S[f][3] = __expf(S[f][3] - mn1);
                s0 += S[f][0] + S[f][1];
                s1 += S[f][2] + S[f][3];
            }
            s0 += __shfl_xor_sync(0xffffffff, s0, 1);
            s0 += __shfl_xor_sync(0xffffffff, s0, 2);
            s1 += __shfl_xor_sync(0xffffffff, s1, 1);
            s1 += __shfl_xor_sync(0xffffffff, s1, 2);
            l[0] = l[0] * a0 + s0;
            l[1] = l[1] * a1 + s1;
            #pragma unroll
            for (int f = 0; f < 8; f++) {
                O[f][0] *= a0; O[f][1] *= a0;
                O[f][2] *= a1; O[f][3] *= a1;
            }

            int kr = (lane & 7) + ((lane & 16) ? 8 : 0);
            int nc8 = (lane & 8) ? 8 : 0;
            #pragma unroll
            for (int kc = 0; kc < 8; kc++) {
                uint32_t pha[4], pla[4];
                #pragma unroll
                for (int q = 0; q < 2; q++) {
                    int f = kc*2 + q;
                    #pragma unroll
                    for (int rh = 0; rh < 2; rh++) {
                        float x = S[f][rh*2], y = S[f][rh*2 + 1];
                        bf16 hx = __float2bfloat16_rn(x);
                        bf16 hy = __float2bfloat16_rn(y);
                        float lx = x - __bfloat162float(hx);
                        float ly = y - __bfloat162float(hy);
                        __nv_bfloat162 ph; ph.x = hx; ph.y = hy;
                        pha[q*2 + rh] = *(uint32_t*)&ph;
                        pla[q*2 + rh] = packbf(lx, ly);
                    }
                }
                #pragma unroll
                for (int ng2 = 0; ng2 < 4; ng2++) {
                    uint32_t va = kb + (uint32_t)((2*FQL) + (kc*16 + kr) * FPAD + ng2*16 + nc8) * 2;
                    uint32_t vH[4], vL[4];
                    ldsm4t(vH[0], vH[1], vH[2], vH[3], va);
                    ldsm4t(vL[0], vL[1], vL[2], vL[3], va + FQL*2);
                    #pragma unroll
                    for (int sub = 0; sub < 2; sub++) {
                        float* c = O[ng2*2 + sub];
                        uint32_t b0 = sub ? vH[1] : vH[0], b1 = sub ? vH[3] : vH[2];
                        uint32_t l0 = sub ? vL[1] : vL[0], l1 = sub ? vL[3] : vL[2];
                        mma16816(c, pha[0], pha[1], pha[2], pha[3], b0, b1);
                        mma16816(c, pla[0], pla[1], pla[2], pla[3], b0, b1);
                        mma16816(c, pha[0], pha[1], pha[2], pha[3], l0, l1);
                    }
                }
            }
            __syncthreads();
        }

        float i0 = 1.f / l[0], i1 = 1.f / l[1];
        int rg0 = grow0 + m0 + r4;
        #pragma unroll
        for (int f = 0; f < 8; f++) {
            int col = h*64 + f*8 + c2;
            float v0 = O[f][0] * i0, v1 = O[f][1] * i0;
            float w0 = O[f][2] * i1, w1 = O[f][3] * i1;
            size_t rS0 = (size_t)rg0 * 1024;
            size_t rS1 = (size_t)(rg0 + 8) * 1024;
            bf16 h0, l0h, h1, l1h;
            split2(v0, h0, l0h); split2(v1, h1, l1h);
            __nv_bfloat162 ph; ph.x = h0; ph.y = h1;
            __nv_bfloat162 pl; pl.x = l0h; pl.y = l1h;
            *(__nv_bfloat162*)&as2[rS0 + col]       = ph;
            *(__nv_bfloat162*)&as2[rS0 + 512 + col] = pl;
            split2(w0, h0, l0h); split2(w1, h1, l1h);
            ph.x = h0; ph.y = h1; pl.x = l0h; pl.y = l1h;
            *(__nv_bfloat162*)&as2[rS1 + col]       = ph;
            *(__nv_bfloat162*)&as2[rS1 + 512 + col] = pl;
        }
        __syncthreads();
    }
}

// ---------------- small kernels --------------------------------------------
__global__ void embed_kernel(const int* __restrict__ idx, const float* __restrict__ tok,
                             const float* __restrict__ pos, float* __restrict__ out) {
    int r = blockIdx.x;
    int t = r & (Td - 1);
    int token = idx[r];
    int c = threadIdx.x;
    const float* tp = tok + (size_t)token * Cd;
    const float* pp = pos + (size_t)t * Cd;
    float* op = out + (size_t)r * Cd;
    op[c] = tp[c] + pp[c];
    op[c + 256] = tp[c + 256] + pp[c + 256];
}

template<bool ADD, bool FOUT>
__global__ void ln_kernel(const float* __restrict__ in, float* __restrict__ out,
                          const float* __restrict__ gw, const float* __restrict__ bw,
                          const float* __restrict__ add, bf16* __restrict__ s2) {
    int r = blockIdx.x;
    const float* x = in + (size_t)r * Cd;
    int tid = threadIdx.x;
    float v0 = x[tid], v1 = x[tid + 256];
    __shared__ float rs[256], rq[256];
    rs[tid] = v0 + v1;
    rq[tid] = v0 * v0 + v1 * v1;
    __syncthreads();
    #pragma unroll
    for (int off = 128; off > 0; off >>= 1) {
        if (tid < off) { rs[tid] += rs[tid+off]; rq[tid] += rq[tid+off]; }
        __syncthreads();
    }
    float mean = rs[0] * (1.0f / Cd);
    float var = rq[0] * (1.0f / Cd) - mean * mean;
    float inv = rsqrtf(var + 1e-5f);
    float o0 = (v0 - mean) * inv * gw[tid] + bw[tid];
    float o1 = (v1 - mean) * inv * gw[tid+256] + bw[tid+256];
    if (ADD) {
        o0 += add[(size_t)r * Cd + tid];
        o1 += add[(size_t)r * Cd + tid + 256];
    }
    if (FOUT) {
        out[(size_t)r * Cd + tid] = o0;
        out[(size_t)r * Cd + tid + 256] = o1;
    }
    bf16 h, l;
    size_t base = (size_t)r * 2 * Cd;
    split2(o0, h, l);
    s2[base + tid] = h; s2[base + Cd + tid] = l;
    split2(o1, h, l);
    s2[base + tid + 256] = h; s2[base + Cd + tid + 256] = l;
}

__global__ void prep_qkv_w(const float* __restrict__ wq, const float* __restrict__ wk,
                           const float* __restrict__ wv, bf16* __restrict__ o2) {
    int i = blockIdx.x * 256 + threadIdx.x;
    if (i >= Ld * QKVW * Cd) return;
    int k = i % Cd;
    int n = (i / Cd) % QKVW;
    int l = i / (Cd * QKVW);
    int which = n >> 9, h = (n >> 6) & 7, d = n & 63;
    const float* src = (which == 0) ? wq : (which == 1) ? wk : wv;
    float v = src[(((size_t)l * Hd + h) * Cd + k) * HSd + d];
    bf16 hh, ll; split2(v, hh, ll);
    size_t base = ((size_t)l * QKVW + n) * 2 * Cd;
    o2[base + k] = hh; o2[base + Cd + k] = ll;
}
__global__ void split_b2(const float* __restrict__ in, bf16* __restrict__ o2,
                         int n, int W) {
    int i = blockIdx.x * 256 + threadIdx.x;
    if (i >= n) return;
    int r = i / W, k = i - r * W;
    bf16 h, l; split2(in[i], h, l);
    size_t base = (size_t)r * 2 * W;
    o2[base + k] = h; o2[base + W + k] = l;
}
__global__ void transpose_b2(const float* __restrict__ in, bf16* __restrict__ o2,
                             int K, int N) {
    __shared__ float tsm[32][33];
    in += (size_t)blockIdx.z * K * N;
    o2 += (size_t)blockIdx.z * N * 2 * K;
    int n0 = blockIdx.x * 32, k0 = blockIdx.y * 32;
    for (int j = threadIdx.y; j < 32; j += 8)
        tsm[j][threadIdx.x] = in[(size_t)(k0 + j) * N + n0 + threadIdx.x];
    __syncthreads();
    for (int i = threadIdx.y; i < 32; i += 8) {
        float v = tsm[threadIdx.x][i];
        bf16 h, l; split2(v, h, l);
        size_t base = (size_t)(n0 + i) * 2 * K;
        int k = k0 + threadIdx.x;
        o2[base + k] = h; o2[base + K + k] = l;
    }
}

// ---------------- host -----------------------------------------------------
extern "C" void kernel_launch(void* const* d_in, const int* in_sizes, int n_in,
                              void* d_out, int out_size) {
    const int*   idx     = (const int*)  d_in[0];
    const float* tok_emb = (const float*)d_in[1];
    const float* pos_emb = (const float*)d_in[2];
    const float* ln1_g   = (const float*)d_in[3];
    const float* ln1_b   = (const float*)d_in[4];
    const float* wq      = (const float*)d_in[5];
    const float* wk      = (const float*)d_in[6];
    const float* wv      = (const float*)d_in[7];
    const float* proj_w  = (const float*)d_in[8];
    const float* proj_b  = (const float*)d_in[9];
    const float* ln2_g   = (const float*)d_in[10];
    const float* ln2_b   = (const float*)d_in[11];
    const float* ff_w1   = (const float*)d_in[12];
    const float* ff_b1   = (const float*)d_in[13];
    const float* ff_w2   = (const float*)d_in[14];
    const float* ff_b2   = (const float*)d_in[15];
    const float* ffln_g  = (const float*)d_in[16];
    const float* ffln_b  = (const float*)d_in[17];
    const float* lm_w    = (const float*)d_in[18];
    const float* lm_b    = (const float*)d_in[19];
    float* out = (float*)d_out;

    float *x, *ff2;
    cudaGetSymbolAddress((void**)&x,   g_x);
    cudaGetSymbolAddress((void**)&ff2, g_ff2);
    bf16 *qkv2, *hs2, *as2, *xs2, *f12, *wqkv2, *wproj2, *wff12, *wff22, *wlm2;
    cudaGetSymbolAddress((void**)&qkv2,  g_qkv2);
    cudaGetSymbolAddress((void**)&hs2,   g_hs2);
    cudaGetSymbolAddress((void**)&as2,   g_as2);
    cudaGetSymbolAddress((void**)&xs2,   g_xs2);
    cudaGetSymbolAddress((void**)&f12,   g_f12);
    cudaGetSymbolAddress((void**)&wqkv2, g_wqkv2);
    cudaGetSymbolAddress((void**)&wproj2,g_wproj2);
    cudaGetSymbolAddress((void**)&wff12, g_wff12);
    cudaGetSymbolAddress((void**)&wff22, g_wff22);
    cudaGetSymbolAddress((void**)&wlm2,  g_wlm2);

    cudaFuncSetAttribute(flash_kernel, cudaFuncAttributeMaxDynamicSharedMemorySize, FLASH_SMEM);
    cudaFuncSetAttribute(hgemm<4,2,false,false,false,false,true>, cudaFuncAttributeMaxDynamicSharedMemorySize, HG_SMEM(4,2));
    cudaFuncSetAttribute(hgemm<2,3,true,false,true,true,false>,  cudaFuncAttributeMaxDynamicSharedMemorySize, HG_SMEM(2,3));
    cudaFuncSetAttribute(hgemm<4,2,true,true,false,false,true>,  cudaFuncAttributeMaxDynamicSharedMemorySize, HG_SMEM(4,2));
    cudaFuncSetAttribute(hgemm<2,3,true,false,false,true,false>, cudaFuncAttributeMaxDynamicSharedMemorySize, HG_SMEM(2,3));
    cudaFuncSetAttribute(hgemm<4,2,true,false,false,true,false>, cudaFuncAttributeMaxDynamicSharedMemorySize, HG_SMEM(4,2));

    embed_kernel<<<NT, 256>>>(idx, tok_emb, pos_emb, x);
    prep_qkv_w<<<(Ld*QKVW*Cd + 255)/256, 256>>>(wq, wk, wv, wqkv2);
    split_b2<<<(Ld*Cd*Cd + 255)/256, 256>>>(proj_w, wproj2, Ld*Cd*Cd, Cd);
    transpose_b2<<<dim3(FFW/32, Cd/32, Ld), dim3(32,8)>>>(ff_w1, wff12, Cd, FFW);
    transpose_b2<<<dim3(Cd/32, FFW/32, Ld), dim3(32,8)>>>(ff_w2, wff22, FFW, Cd);
    transpose_b2<<<dim3(Vd/32, Cd/32, 1),  dim3(32,8)>>>(lm_w, wlm2, Cd, Vd);

    for (int l = 0; l < Ld; l++) {
        ln_kernel<false,false><<<NT, 256>>>(x, nullptr, ln1_g + l*Cd, ln1_b + l*Cd,
                                            nullptr, hs2);
        hgemm<4,2,false,false,false,false,true><<<dim3(NT/128, QKVW/128), 256, HG_SMEM(4,2)>>>(
            hs2, wqkv2 + (size_t)l*QKVW*2*Cd, nullptr, nullptr, nullptr, qkv2,
            NT, QKVW, Cd);
        flash_kernel<<<148, 256, FLASH_SMEM>>>(qkv2, as2);
        hgemm<2,3,true,false,true,true,false><<<dim3(NT/64, Cd/128), 256, HG_SMEM(2,3)>>>(
            as2, wproj2 + (size_t)l*Cd*2*Cd, x, proj_b + l*Cd, x, nullptr,
            NT, Cd, Cd);
        ln_kernel<false,false><<<NT, 256>>>(x, nullptr, ln2_g + l*Cd, ln2_b + l*Cd,
                                            nullptr, hs2);
        hgemm<4,2,true,true,false,false,true><<<dim3(NT/128, FFW/128), 256, HG_SMEM(4,2)>>>(
            hs2, wff12 + (size_t)l*FFW*2*Cd, nullptr, ff_b1 + l*FFW, nullptr, f12,
            NT, FFW, Cd);
        hgemm<2,3,true,false,false,true,false><<<dim3(NT/64, Cd/128), 256, HG_SMEM(2,3)>>>(
            f12, wff22 + (size_t)l*Cd*2*FFW, ff2, ff_b2 + l*Cd, nullptr, nullptr,
            NT, Cd, FFW);
        ln_kernel<true,true><<<NT, 256>>>(ff2, x, ffln_g + l*Cd, ffln_b + l*Cd,
                                          x, xs2);
    }
    hgemm<4,2,true,false,false,true,false><<<dim3(NT/128, Vd/128), 256, HG_SMEM(4,2)>>>(
        xs2, wlm2, out, lm_b, nullptr, nullptr, NT, Vd, Cd);
}